// round 12
// baseline (speedup 1.0000x reference)
#include <cuda_runtime.h>
#include <cuda_bf16.h>
#include <stdint.h>
#include <math.h>

// ---------------------------------------------------------------------------
// RWKV7 attention block, B=4 T=2048 H=1024 NH=16 HD=64.
// Big GEMMs on mma.sync bf16 (hi+lo split, fp32 accum) — tcgen05 unavailable
// (harness emits compute_103 PTX). LoRA-down GEMMs on fp32 SGEMM;
// ring-buffered sequential scan; fused epilogues.
// ---------------------------------------------------------------------------

#define BB   4
#define TT   2048
#define HH   1024
#define HDD  64
#define NHH  16
#define BT   (BB*TT)        // 8192 tokens
#define BTH  (BT*HH)        // 8388608
#define DECAY_LOG_SCALE (-0.6065306597126334f)
#define GN_EPS (64.0f*1e-5f)

// ----------------------------- scratch ------------------------------------
static __device__ float g_xr[BTH], g_xw[BTH], g_xk[BTH], g_xv[BTH], g_xa[BTH], g_xg[BTH];
static __device__ float g_r[BTH], g_ew[BTH], g_k[BTH], g_v0[BTH], g_v[BTH], g_a[BTH];
static __device__ float g_an[BTH], g_bv[BTH], g_g[BTH], g_o[BTH], g_y[BTH];
static __device__ float g_t1[BT*64], g_t2[BT*64], g_t3[BT*64], g_t4[BT*160];

// transposed + bf16-split weights ([N,K] K-major)
static __device__ __nv_bfloat16 g_WrH[HH*HH], g_WrL[HH*HH];
static __device__ __nv_bfloat16 g_WkH[HH*HH], g_WkL[HH*HH];
static __device__ __nv_bfloat16 g_WvH[HH*HH], g_WvL[HH*HH];
static __device__ __nv_bfloat16 g_WoH[HH*HH], g_WoL[HH*HH];
static __device__ __nv_bfloat16 g_wBH[HH*64], g_wBL[HH*64];
static __device__ __nv_bfloat16 g_vBH[HH*64], g_vBL[HH*64];
static __device__ __nv_bfloat16 g_aBH[HH*64], g_aBL[HH*64];
static __device__ __nv_bfloat16 g_gBH[HH*160], g_gBL[HH*160];

__device__ __forceinline__ float sigf(float x) { return 1.0f / (1.0f + expf(-x)); }

__device__ __forceinline__ uint32_t pack_bf2(__nv_bfloat16 lo, __nv_bfloat16 hi) {
    return (uint32_t)__bfloat16_as_ushort(lo) | ((uint32_t)__bfloat16_as_ushort(hi) << 16);
}

__device__ __forceinline__ uint32_t smem_u32(const void* p) {
    uint32_t a;
    asm("{ .reg .u64 t; cvta.to.shared.u64 t, %1; cvt.u32.u64 %0, t; }" : "=r"(a) : "l"(p));
    return a;
}

__device__ __forceinline__ void ldsm4(uint32_t& r0, uint32_t& r1, uint32_t& r2, uint32_t& r3,
                                      uint32_t addr)
{
    asm volatile("ldmatrix.sync.aligned.m8n8.x4.shared.b16 {%0,%1,%2,%3}, [%4];"
                 : "=r"(r0), "=r"(r1), "=r"(r2), "=r"(r3) : "r"(addr));
}

__device__ __forceinline__ void mma16816(float* c,
                                         uint32_t a0, uint32_t a1, uint32_t a2, uint32_t a3,
                                         uint32_t b0, uint32_t b1)
{
    asm volatile("mma.sync.aligned.m16n8k16.row.col.f32.bf16.bf16.f32 "
                 "{%0,%1,%2,%3}, {%4,%5,%6,%7}, {%8,%9}, {%0,%1,%2,%3};"
                 : "+f"(c[0]), "+f"(c[1]), "+f"(c[2]), "+f"(c[3])
                 : "r"(a0), "r"(a1), "r"(a2), "r"(a3), "r"(b0), "r"(b1));
}

// ----------------------------- prep: token shift ---------------------------
__global__ void prep_kernel(const float* __restrict__ hs,
                            const float* __restrict__ mr, const float* __restrict__ mw,
                            const float* __restrict__ mk, const float* __restrict__ mv,
                            const float* __restrict__ ma, const float* __restrict__ mg)
{
    int i4 = blockIdx.x * blockDim.x + threadIdx.x;
    if (i4 >= BTH / 4) return;
    int i = i4 * 4;
    int t = (i / HH) % TT;
    int h = i % HH;
    float4 x = *(const float4*)(hs + i);
    float4 p = make_float4(0.f, 0.f, 0.f, 0.f);
    if (t > 0) p = *(const float4*)(hs + i - HH);
    float4 d = make_float4(p.x - x.x, p.y - x.y, p.z - x.z, p.w - x.w);
#define DOMIX(dst, mp) { float4 m4 = *(const float4*)((mp) + h); float4 o4; \
    o4.x = fmaf(d.x, m4.x, x.x); o4.y = fmaf(d.y, m4.y, x.y); \
    o4.z = fmaf(d.z, m4.z, x.z); o4.w = fmaf(d.w, m4.w, x.w); \
    *(float4*)((dst) + i) = o4; }
    DOMIX(g_xr, mr) DOMIX(g_xw, mw) DOMIX(g_xk, mk)
    DOMIX(g_xv, mv) DOMIX(g_xa, ma) DOMIX(g_xg, mg)
#undef DOMIX
}

// ----------------- weight transpose + bf16 hi/lo split (all-in-one) -------
// Each 32x32 tile of each weight matrix handled by one block; 1D grid decode.
// Sources are the UP-projection matrices: W_r/W_k/W_v/W_o (1024xK rows) and
// wB/vB/aB (64x1024), gB (160x1024).
__global__ void convw_all_kernel(const float* __restrict__ Wr, const float* __restrict__ Wk,
                                 const float* __restrict__ Wv, const float* __restrict__ Wo,
                                 const float* __restrict__ wB, const float* __restrict__ vB,
                                 const float* __restrict__ aB, const float* __restrict__ gB)
{
    __shared__ float ts[32][33];
    int bidx = blockIdx.x;
    const float* W; __nv_bfloat16 *Bh, *Bl; int K, local;
    if (bidx < 4096) {
        int m = bidx >> 10; local = bidx & 1023; K = HH;
        switch (m) {
            case 0: W = Wr; Bh = g_WrH; Bl = g_WrL; break;
            case 1: W = Wk; Bh = g_WkH; Bl = g_WkL; break;
            case 2: W = Wv; Bh = g_WvH; Bl = g_WvL; break;
            default: W = Wo; Bh = g_WoH; Bl = g_WoL; break;
        }
    } else if (bidx < 4288) {
        int m = (bidx - 4096) >> 6; local = (bidx - 4096) & 63; K = 64;
        switch (m) {
            case 0: W = wB; Bh = g_wBH; Bl = g_wBL; break;
            case 1: W = vB; Bh = g_vBH; Bl = g_vBL; break;
            default: W = aB; Bh = g_aBH; Bl = g_aBL; break;
        }
    } else {
        local = bidx - 4288; K = 160;
        W = gB; Bh = g_gBH; Bl = g_gBL;
    }
    const int N = HH;
    int nb = (local & 31) * 32, kb = (local >> 5) * 32;
    int tx = threadIdx.x, ty = threadIdx.y;  // 32 x 8
    for (int i = ty; i < 32; i += 8)
        ts[i][tx] = W[(size_t)(kb + i) * N + nb + tx];
    __syncthreads();
    for (int i = ty; i < 32; i += 8) {
        float x = ts[tx][i];                 // W[kb+tx][nb+i]
        __nv_bfloat16 h = __float2bfloat16(x);
        __nv_bfloat16 l = __float2bfloat16(x - __bfloat162float(h));
        size_t o = (size_t)(nb + i) * K + kb + tx;
        Bh[o] = h; Bl[o] = l;
    }
}

// --------------------- mma.sync GEMM: C = A @ Bt^T -------------------------
// A: (M,K) fp32, split on the fly to bf16 hi/lo. Bt: (N,K) bf16 hi/lo.
// CTA tile 128x128, BK=32, 8 warps (2x4), warp tile 64x32.
// 3-product split: Ah*Bh + Ah*Bl + Al*Bh in fp32 accumulators.
// EPI: 0 none, 3 sigmoid(+bias), 4 exp(DECAY*sigmoid(+bias)),
//      5 v-lerp e0 + sig(acc+bias)*(e1-e0)
#define LDS 40                       // padded row length (bf16 elems)
#define ABUF (128*LDS)               // elems per matrix (one of hi/lo)
#define TG_SMEM (4*ABUF*2*2)         // A(2bufs:hi+lo) + B(2bufs:hi+lo) = 81920 B

template <int EPI>
__global__ void __launch_bounds__(256)
tgemm_kernel(const float* __restrict__ A,
             const __nv_bfloat16* __restrict__ Bh, const __nv_bfloat16* __restrict__ Bl,
             float* __restrict__ C, int M, int N, int K,
             const float* __restrict__ bias,
             const float* __restrict__ e0, const float* __restrict__ e1)
{
    extern __shared__ char smem[];
    __nv_bfloat16* As = (__nv_bfloat16*)smem;             // [2 bufs][2 hl][128][LDS]
    __nv_bfloat16* Bs = (__nv_bfloat16*)(smem + 2*2*ABUF*2);
    const int tid = threadIdx.x;
    const int wid = tid >> 5, lane = tid & 31;
    const int wm = wid >> 2, wn = wid & 3;
    const int m0 = blockIdx.y * 128, n0 = blockIdx.x * 128;

    float acc[4][4][4];
#pragma unroll
    for (int i = 0; i < 4; i++)
#pragma unroll
        for (int j = 0; j < 4; j++)
#pragma unroll
            for (int f = 0; f < 4; f++) acc[i][j][f] = 0.f;

    float4 aReg[4];
    uint4 bhReg[2], blReg[2];

    const int nC = K >> 5;

#define LOAD_REGS(kc) { \
        int k0 = (kc) << 5; \
        _Pragma("unroll") \
        for (int i = 0; i < 4; i++) { \
            int idx = tid + i * 256; \
            int r = idx >> 3, c4 = (idx & 7) << 2; \
            aReg[i] = *(const float4*)(A + (size_t)(m0 + r) * K + k0 + c4); \
        } \
        _Pragma("unroll") \
        for (int i = 0; i < 2; i++) { \
            int idx = tid + i * 256; \
            int r = idx >> 2, c8 = (idx & 3) << 3; \
            size_t go = (size_t)(n0 + r) * K + k0 + c8; \
            bhReg[i] = *(const uint4*)(Bh + go); \
            blReg[i] = *(const uint4*)(Bl + go); \
        } }

#define STORE_SMEM(b) { \
        __nv_bfloat16* aH = As + (b) * 2 * ABUF; \
        __nv_bfloat16* aL = aH + ABUF; \
        __nv_bfloat16* bH = Bs + (b) * 2 * ABUF; \
        __nv_bfloat16* bL = bH + ABUF; \
        _Pragma("unroll") \
        for (int i = 0; i < 4; i++) { \
            int idx = tid + i * 256; \
            int r = idx >> 3, c4 = (idx & 7) << 2; \
            float4 v = aReg[i]; \
            __nv_bfloat16 hx = __float2bfloat16(v.x); \
            __nv_bfloat16 hy = __float2bfloat16(v.y); \
            __nv_bfloat16 hz = __float2bfloat16(v.z); \
            __nv_bfloat16 hw = __float2bfloat16(v.w); \
            __nv_bfloat16 lx = __float2bfloat16(v.x - __bfloat162float(hx)); \
            __nv_bfloat16 ly = __float2bfloat16(v.y - __bfloat162float(hy)); \
            __nv_bfloat16 lz = __float2bfloat16(v.z - __bfloat162float(hz)); \
            __nv_bfloat16 lw = __float2bfloat16(v.w - __bfloat162float(hw)); \
            uint2 hv2, lv2; \
            hv2.x = pack_bf2(hx, hy); hv2.y = pack_bf2(hz, hw); \
            lv2.x = pack_bf2(lx, ly); lv2.y = pack_bf2(lz, lw); \
            *(uint2*)(aH + r * LDS + c4) = hv2; \
            *(uint2*)(aL + r * LDS + c4) = lv2; \
        } \
        _Pragma("unroll") \
        for (int i = 0; i < 2; i++) { \
            int idx = tid + i * 256; \
            int r = idx >> 2, c8 = (idx & 3) << 3; \
            *(uint4*)(bH + r * LDS + c8) = bhReg[i]; \
            *(uint4*)(bL + r * LDS + c8) = blReg[i]; \
        } }

    LOAD_REGS(0)
    STORE_SMEM(0)
    __syncthreads();

    for (int ic = 0; ic < nC; ic++) {
        int buf = ic & 1;
        if (ic + 1 < nC) LOAD_REGS(ic + 1)

        {
            uint32_t aBaseH = smem_u32(As + buf * 2 * ABUF);
            uint32_t aBaseL = aBaseH + ABUF * 2;
            uint32_t bBaseH = smem_u32(Bs + buf * 2 * ABUF);
            uint32_t bBaseL = bBaseH + ABUF * 2;
#pragma unroll
            for (int kk = 0; kk < 32; kk += 16) {
                uint32_t ah[4][4], al[4][4], bh[2][4], bl[2][4];
#pragma unroll
                for (int i = 0; i < 4; i++) {
                    int row = wm * 64 + i * 16 + (lane & 15);
                    int col = kk + ((lane >> 4) << 3);
                    uint32_t off = (uint32_t)(row * LDS + col) * 2;
                    ldsm4(ah[i][0], ah[i][1], ah[i][2], ah[i][3], aBaseH + off);
                    ldsm4(al[i][0], al[i][1], al[i][2], al[i][3], aBaseL + off);
                }
#pragma unroll
                for (int jp = 0; jp < 2; jp++) {
                    int row = wn * 32 + jp * 16 + ((lane >> 4) << 3) + (lane & 7);
                    int col = kk + ((lane >> 3) & 1) * 8;
                    uint32_t off = (uint32_t)(row * LDS + col) * 2;
                    ldsm4(bh[jp][0], bh[jp][1], bh[jp][2], bh[jp][3], bBaseH + off);
                    ldsm4(bl[jp][0], bl[jp][1], bl[jp][2], bl[jp][3], bBaseL + off);
                }
#pragma unroll
                for (int i = 0; i < 4; i++)
#pragma unroll
                    for (int j = 0; j < 4; j++) {
                        uint32_t b0h = bh[j >> 1][(j & 1) * 2], b1h = bh[j >> 1][(j & 1) * 2 + 1];
                        uint32_t b0l = bl[j >> 1][(j & 1) * 2], b1l = bl[j >> 1][(j & 1) * 2 + 1];
                        mma16816(acc[i][j], ah[i][0], ah[i][1], ah[i][2], ah[i][3], b0h, b1h);
                        mma16816(acc[i][j], ah[i][0], ah[i][1], ah[i][2], ah[i][3], b0l, b1l);
                        mma16816(acc[i][j], al[i][0], al[i][1], al[i][2], al[i][3], b0h, b1h);
                    }
            }
        }

        if (ic + 1 < nC) {
            __syncthreads();
            STORE_SMEM(buf ^ 1)
            __syncthreads();
        }
    }

    // ---- epilogue ----
    int g = lane >> 2, tig = lane & 3;
#pragma unroll
    for (int i = 0; i < 4; i++) {
        int r0 = m0 + wm * 64 + i * 16 + g;
#pragma unroll
        for (int j = 0; j < 4; j++) {
            int col = n0 + wn * 32 + j * 8 + tig * 2;
            float2 v0 = make_float2(acc[i][j][0], acc[i][j][1]);
            float2 v1 = make_float2(acc[i][j][2], acc[i][j][3]);
            if (EPI == 3 || EPI == 4 || EPI == 5) {
                float b0 = bias[col], b1 = bias[col + 1];
                v0.x = sigf(v0.x + b0); v0.y = sigf(v0.y + b1);
                v1.x = sigf(v1.x + b0); v1.y = sigf(v1.y + b1);
                if (EPI == 4) {
                    v0.x = expf(DECAY_LOG_SCALE * v0.x); v0.y = expf(DECAY_LOG_SCALE * v0.y);
                    v1.x = expf(DECAY_LOG_SCALE * v1.x); v1.y = expf(DECAY_LOG_SCALE * v1.y);
                } else if (EPI == 5) {
                    size_t o0 = (size_t)r0 * N + col, o1 = (size_t)(r0 + 8) * N + col;
                    float2 a0 = *(const float2*)(e0 + o0);
                    float2 c0v = *(const float2*)(e1 + o0);
                    float2 a1 = *(const float2*)(e0 + o1);
                    float2 c1v = *(const float2*)(e1 + o1);
                    v0.x = fmaf(v0.x, c0v.x - a0.x, a0.x);
                    v0.y = fmaf(v0.y, c0v.y - a0.y, a0.y);
                    v1.x = fmaf(v1.x, c1v.x - a1.x, a1.x);
                    v1.y = fmaf(v1.y, c1v.y - a1.y, a1.y);
                }
            }
            *(float2*)(C + (size_t)r0 * N + col) = v0;
            *(float2*)(C + (size_t)(r0 + 8) * N + col) = v1;
        }
    }
}

// ----------------------------- SGEMM (fp32, 64x64x16 tile) -----------------
// EPI: 0 none, 1 tanh, 2 sigmoid
template <int EPI>
__global__ void __launch_bounds__(256)
sgemm_kernel(const float* __restrict__ A, const float* __restrict__ Bm,
             float* __restrict__ C, int M, int N, int K)
{
    constexpr int BK = 16;
    __shared__ float As[BK][68];
    __shared__ float Bs[BK][64];
    int tid = threadIdx.x;
    int tx = tid & 15, ty = tid >> 4;
    int m0 = blockIdx.y * 64, n0 = blockIdx.x * 64;
    int ar = tid >> 2, ac = (tid & 3) << 2;
    int br = tid >> 4, bc = (tid & 15) << 2;
    float acc[4][4];
#pragma unroll
    for (int i = 0; i < 4; i++)
#pragma unroll
        for (int j = 0; j < 4; j++) acc[i][j] = 0.f;

    const float* Ap = A + (size_t)(m0 + ar) * K + ac;
    const float* Bp = Bm + (size_t)br * N + n0 + bc;
    bool bvalid = (n0 + bc) < N;

    for (int k0 = 0; k0 < K; k0 += BK) {
        float4 av = *(const float4*)(Ap + k0);
        As[ac + 0][ar] = av.x; As[ac + 1][ar] = av.y;
        As[ac + 2][ar] = av.z; As[ac + 3][ar] = av.w;
        float4 bv4 = make_float4(0.f, 0.f, 0.f, 0.f);
        if (bvalid) bv4 = *(const float4*)(Bp + (size_t)k0 * N);
        *(float4*)&Bs[br][bc] = bv4;
        __syncthreads();
#pragma unroll
        for (int kk = 0; kk < BK; kk++) {
            float4 a4 = *(const float4*)&As[kk][ty << 2];
            float4 b4 = *(const float4*)&Bs[kk][tx << 2];
            float aa[4] = {a4.x, a4.y, a4.z, a4.w};
            float bb[4] = {b4.x, b4.y, b4.z, b4.w};
#pragma unroll
            for (int i = 0; i < 4; i++)
#pragma unroll
                for (int j = 0; j < 4; j++)
                    acc[i][j] = fmaf(aa[i], bb[j], acc[i][j]);
        }
        __syncthreads();
    }

#pragma unroll
    for (int i = 0; i < 4; i++) {
        int row = m0 + (ty << 2) + i;
#pragma unroll
        for (int j = 0; j < 4; j++) {
            int col = n0 + (tx << 2) + j;
            if (col < N) {
                float val = acc[i][j];
                if (EPI == 1) val = tanhf(val);
                else if (EPI == 2) val = sigf(val);
                C[(size_t)row * N + col] = val;
            }
        }
    }
}

// --------------------- postproj: kk-normalize, k scale, a/b vecs -----------
__global__ void postproj_kernel(const float* __restrict__ kkw,
                                const float* __restrict__ kaw)
{
    int bt = blockIdx.x;
    int h = threadIdx.x;
    int head = h >> 6;
    int idx = bt * HH + h;
    float kv = g_k[idx], av = g_a[idx];
    float kkx = kv * kkw[h];
    float ss = kkx * kkx;
#pragma unroll
    for (int m = 16; m >= 1; m >>= 1) ss += __shfl_xor_sync(~0u, ss, m);
    __shared__ float ws[32];
    if ((h & 31) == 0) ws[h >> 5] = ss;
    __syncthreads();
    float tot = ws[head * 2] + ws[head * 2 + 1];
    float inv = 1.0f / fmaxf(sqrtf(tot), 1e-12f);
    float kkn = kkx * inv;
    g_an[idx] = -kkn;
    g_bv[idx] = kkn * av;
    g_k[idx] = kv * (1.0f + (av - 1.0f) * kaw[h]);
}

// ----------------------------- sequential scan ------------------------------
// Ring-buffered: 2 groups of 8 timesteps; prefetch next group into registers
// before consuming, store after, one __syncthreads per 8 steps.
__global__ void __launch_bounds__(256) scan_kernel()
{
    __shared__ float sh[2][8][6][64];   // [buf][step][array][channel] = 24 KB
    int pair = blockIdx.x >> 1;
    int rsplit = blockIdx.x & 1;
    int tid = threadIdx.x;
    int vloc = tid >> 3;
    int q = tid & 7;
    int vrow = rsplit * 32 + vloc;
    int b = pair >> 4, h = pair & 15;
    int base0 = b * TT * HH + h * HDD;

    const float* lp = nullptr;
    int aid = 0, wq = 0;
    if (tid < 96) {
        aid = tid >> 4; wq = tid & 15;
        switch (aid) {
            case 0: lp = g_r;  break;
            case 1: lp = g_ew; break;
            case 2: lp = g_k;  break;
            case 3: lp = g_v;  break;
            case 4: lp = g_an; break;
            default: lp = g_bv; break;
        }
        lp += base0 + (wq << 2);
    }

    float S[8];
#pragma unroll
    for (int j = 0; j < 8; j++) S[j] = 0.f;

    // preload group 0
    if (tid < 96) {
#pragma unroll
        for (int s = 0; s < 8; s++)
            *(float4*)&sh[0][s][aid][wq << 2] = *(const float4*)(lp + (size_t)s * HH);
    }
    __syncthreads();

    const int nG = TT / 8;   // 256 groups
    for (int gi = 0; gi < nG; gi++) {
        int cur = gi & 1;

        // issue prefetch loads for next group (no smem store yet)
        float4 pf[8];
        if (tid < 96 && gi + 1 < nG) {
            const float* src = lp + (size_t)((gi + 1) * 8) * HH;
#pragma unroll
            for (int s = 0; s < 8; s++)
                pf[s] = *(const float4*)(src + (size_t)s * HH);
        }

        // consume 8 steps
#pragma unroll
        for (int s = 0; s < 8; s++) {
            const float (*cs)[64] = sh[cur][s];
            int c0 = q << 3;

            float4 aA = *(const float4*)&cs[4][c0];
            float4 aB = *(const float4*)&cs[4][c0 + 4];
            float sa = S[0]*aA.x + S[1]*aA.y + S[2]*aA.z + S[3]*aA.w
                     + S[4]*aB.x + S[5]*aB.y + S[6]*aB.z + S[7]*aB.w;
            sa += __shfl_xor_sync(~0u, sa, 1);
            sa += __shfl_xor_sync(~0u, sa, 2);
            sa += __shfl_xor_sync(~0u, sa, 4);

            float vv = cs[3][vrow];
            float4 eA = *(const float4*)&cs[1][c0];
            float4 eB = *(const float4*)&cs[1][c0 + 4];
            float4 kA = *(const float4*)&cs[2][c0];
            float4 kB = *(const float4*)&cs[2][c0 + 4];
            float4 bA = *(const float4*)&cs[5][c0];
            float4 bB = *(const float4*)&cs[5][c0 + 4];

            S[0] = fmaf(S[0], eA.x, fmaf(sa, bA.x, vv * kA.x));
            S[1] = fmaf(S[1], eA.y, fmaf(sa, bA.y, vv * kA.y));
            S[2] = fmaf(S[2], eA.z, fmaf(sa, bA.z, vv * kA.z));
            S[3] = fmaf(S[3], eA.w, fmaf(sa, bA.w, vv * kA.w));
            S[4] = fmaf(S[4], eB.x, fmaf(sa, bB.x, vv * kB.x));
            S[5] = fmaf(S[5], eB.y, fmaf(sa, bB.y, vv * kB.y));
            S[6] = fmaf(S[6], eB.z, fmaf(sa, bB.z, vv * kB.z));
            S[7] = fmaf(S[7], eB.w, fmaf(sa, bB.w, vv * kB.w));

            float4 rA = *(const float4*)&cs[0][c0];
            float4 rB = *(const float4*)&cs[0][c0 + 4];
            float oo = S[0]*rA.x + S[1]*rA.y + S[2]*rA.z + S[3]*rA.w
                     + S[4]*rB.x + S[5]*rB.y + S[6]*rB.z + S[7]*rB.w;
            oo += __shfl_xor_sync(~0u, oo, 1);
            oo += __shfl_xor_sync(~0u, oo, 2);
            oo += __shfl_xor_sync(~0u, oo, 4);
            if (q == 0) g_o[base0 + (gi * 8 + s) * HH + vrow] = oo;
        }

        // store prefetched group into the buffer consumed last iteration
        if (tid < 96 && gi + 1 < nG) {
#pragma unroll
            for (int s = 0; s < 8; s++)
                *(float4*)&sh[cur ^ 1][s][aid][wq << 2] = pf[s];
        }
        __syncthreads();
    }
}

// ---------------- groupnorm + bonus-corr + gate -> y ------------------------
__global__ void finalmix_kernel(const float* __restrict__ rkw,
                                const float* __restrict__ gnw,
                                const float* __restrict__ gnb)
{
    int bt = blockIdx.x;
    int head = threadIdx.x >> 5;
    int ld = threadIdx.x & 31;
    int base = bt * HH + head * HDD;
    int i0 = base + ld, i1 = base + 32 + ld;
    float o0 = g_o[i0], o1 = g_o[i1];
    float r0 = g_r[i0], r1 = g_r[i1];
    float k0 = g_k[i0], k1 = g_k[i1];
    float v0 = g_v[i0], v1 = g_v[i1];
    int h0 = head * HDD + ld, h1 = h0 + 32;

    float s  = o0 + o1;
    float qq = o0 * o0 + o1 * o1;
    float rk = r0 * k0 * rkw[h0] + r1 * k1 * rkw[h1];
#pragma unroll
    for (int m = 16; m >= 1; m >>= 1) {
        s  += __shfl_xor_sync(~0u, s,  m);
        qq += __shfl_xor_sync(~0u, qq, m);
        rk += __shfl_xor_sync(~0u, rk, m);
    }
    float mu = s * (1.0f / 64.0f);
    float var = qq * (1.0f / 64.0f) - mu * mu;
    float is = rsqrtf(var + GN_EPS);
    float y0 = (fmaf((o0 - mu) * is, gnw[h0], gnb[h0]) + rk * v0) * g_g[i0];
    float y1 = (fmaf((o1 - mu) * is, gnw[h1], gnb[h1]) + rk * v1) * g_g[i1];
    g_y[i0] = y0;
    g_y[i1] = y1;
}

// ----------------------------- host ----------------------------------------
extern "C" void kernel_launch(void* const* d_in, const int* in_sizes, int n_in,
                              void* d_out, int out_size)
{
    const float* hs  = (const float*)d_in[0];
    const float* vfi = (const float*)d_in[1];
    const float* x_r = (const float*)d_in[2];
    const float* x_w = (const float*)d_in[3];
    const float* x_k = (const float*)d_in[4];
    const float* x_v = (const float*)d_in[5];
    const float* x_a = (const float*)d_in[6];
    const float* x_g = (const float*)d_in[7];
    const float* k_k = (const float*)d_in[8];
    const float* k_a = (const float*)d_in[9];
    const float* r_k = (const float*)d_in[10];
    const float* W_r = (const float*)d_in[11];
    const float* W_k = (const float*)d_in[12];
    const float* W_v = (const float*)d_in[13];
    const float* W_o = (const float*)d_in[14];
    const float* wA  = (const float*)d_in[15];
    const float* wB  = (const float*)d_in[16];
    const float* wb  = (const float*)d_in[17];
    const float* vA  = (const float*)d_in[18];
    const float* vB  = (const float*)d_in[19];
    const float* vb  = (const float*)d_in[20];
    const float* aA  = (const float*)d_in[21];
    const float* aB  = (const float*)d_in[22];
    const float* ab  = (const float*)d_in[23];
    const float* gA  = (const float*)d_in[24];
    const float* gB  = (const float*)d_in[25];
    const float* gnw = (const float*)d_in[26];
    const float* gnb = (const float*)d_in[27];

    float *xr, *xw, *xk, *xv, *xa, *xg, *rb, *ewb, *kb, *v0b, *vb2, *ab2;
    float *t1, *t2, *t3, *t4, *gb2, *yb;
    cudaGetSymbolAddress((void**)&xr,  g_xr);
    cudaGetSymbolAddress((void**)&xw,  g_xw);
    cudaGetSymbolAddress((void**)&xk,  g_xk);
    cudaGetSymbolAddress((void**)&xv,  g_xv);
    cudaGetSymbolAddress((void**)&xa,  g_xa);
    cudaGetSymbolAddress((void**)&xg,  g_xg);
    cudaGetSymbolAddress((void**)&rb,  g_r);
    cudaGetSymbolAddress((void**)&ewb, g_ew);
    cudaGetSymbolAddress((void**)&kb,  g_k);
    cudaGetSymbolAddress((void**)&v0b, g_v0);
    cudaGetSymbolAddress((void**)&vb2, g_v);
    cudaGetSymbolAddress((void**)&ab2, g_a);
    cudaGetSymbolAddress((void**)&t1,  g_t1);
    cudaGetSymbolAddress((void**)&t2,  g_t2);
    cudaGetSymbolAddress((void**)&t3,  g_t3);
    cudaGetSymbolAddress((void**)&t4,  g_t4);
    cudaGetSymbolAddress((void**)&gb2, g_g);
    cudaGetSymbolAddress((void**)&yb,  g_y);

    __nv_bfloat16 *WrH, *WrL, *WkH, *WkL, *WvH, *WvL, *WoH, *WoL;
    __nv_bfloat16 *wBH, *wBL, *vBH, *vBL, *aBH, *aBL, *gBH, *gBL;
    cudaGetSymbolAddress((void**)&WrH, g_WrH); cudaGetSymbolAddress((void**)&WrL, g_WrL);
    cudaGetSymbolAddress((void**)&WkH, g_WkH); cudaGetSymbolAddress((void**)&WkL, g_WkL);
    cudaGetSymbolAddress((void**)&WvH, g_WvH); cudaGetSymbolAddress((void**)&WvL, g_WvL);
    cudaGetSymbolAddress((void**)&WoH, g_WoH); cudaGetSymbolAddress((void**)&WoL, g_WoL);
    cudaGetSymbolAddress((void**)&wBH, g_wBH); cudaGetSymbolAddress((void**)&wBL, g_wBL);
    cudaGetSymbolAddress((void**)&vBH, g_vBH); cudaGetSymbolAddress((void**)&vBL, g_vBL);
    cudaGetSymbolAddress((void**)&aBH, g_aBH); cudaGetSymbolAddress((void**)&aBL, g_aBL);
    cudaGetSymbolAddress((void**)&gBH, g_gBH); cudaGetSymbolAddress((void**)&gBL, g_gBL);

    cudaFuncSetAttribute(tgemm_kernel<0>, cudaFuncAttributeMaxDynamicSharedMemorySize, TG_SMEM);
    cudaFuncSetAttribute(tgemm_kernel<3>, cudaFuncAttributeMaxDynamicSharedMemorySize, TG_SMEM);
    cudaFuncSetAttribute(tgemm_kernel<4>, cudaFuncAttributeMaxDynamicSharedMemorySize, TG_SMEM);
    cudaFuncSetAttribute(tgemm_kernel<5>, cudaFuncAttributeMaxDynamicSharedMemorySize, TG_SMEM);

    dim3 blk(256);
    dim3 gT(HH / 128, BT / 128);       // 8 x 64 mma-GEMM tiles
    dim3 g64(1, BT / 64);
    dim3 g160(3, BT / 64);
    dim3 cblk(32, 8);

    // launch 0: all weight transposes + bf16 splits in one kernel
    // sources: the UP-projection matrices wB/vB/aB/gB (NOT wA/vA/aA/gA).
    convw_all_kernel<<<4448, cblk>>>(W_r, W_k, W_v, W_o, wB, vB, aB, gB);

    // launch 1: token-shift mixes
    prep_kernel<<<BTH / 4 / 256, 256>>>(hs, x_r, x_w, x_k, x_v, x_a, x_g);

    // launches 2-4: LoRA down-projections (depend only on prep)
    sgemm_kernel<1><<<g64, blk>>>(xw, wA, t1, BT, 64, HH);                  // tanh
    sgemm_kernel<0><<<g64, blk>>>(xv, vA, t2, BT, 64, HH);
    sgemm_kernel<0><<<g64, blk>>>(xa, aA, t3, BT, 64, HH);

    // launch 5: r projection  (ncu -s 5 -c 1 captures THIS one)
    tgemm_kernel<0><<<gT, blk, TG_SMEM>>>(xr, WrH, WrL, rb,  BT, HH, HH, nullptr, nullptr, nullptr);
    // launches 6-7: k / v projections
    tgemm_kernel<0><<<gT, blk, TG_SMEM>>>(xk, WkH, WkL, kb,  BT, HH, HH, nullptr, nullptr, nullptr);
    tgemm_kernel<0><<<gT, blk, TG_SMEM>>>(xv, WvH, WvL, v0b, BT, HH, HH, nullptr, nullptr, nullptr);

    // launch 8: gate down-projection
    sgemm_kernel<2><<<g160, blk>>>(xg, gA, t4, BT, 160, HH);                // sigmoid

    // launches 9-12: LoRA/gate up-projections with fused epilogues
    tgemm_kernel<4><<<gT, blk, TG_SMEM>>>(t1, wBH, wBL, ewb, BT, HH, 64, wb, nullptr, nullptr);
    tgemm_kernel<5><<<gT, blk, TG_SMEM>>>(t2, vBH, vBL, vb2, BT, HH, 64, vb, v0b, vfi);
    tgemm_kernel<3><<<gT, blk, TG_SMEM>>>(t3, aBH, aBL, ab2, BT, HH, 64, ab, nullptr, nullptr);
    tgemm_kernel<0><<<gT, blk, TG_SMEM>>>(t4, gBH, gBL, gb2, BT, HH, 160, nullptr, nullptr, nullptr);

    // launch 13: kk normalize / k scale / scan coefficient vectors
    postproj_kernel<<<BT, 1024>>>(k_k, k_a);

    // launch 14: sequential RWKV7 scan (ring-buffered)
    scan_kernel<<<128, 256>>>();

    // launch 15: groupnorm + correction + gate
    finalmix_kernel<<<BT, 512>>>(r_k, gnw, gnb);

    // launch 16: output projection
    tgemm_kernel<0><<<gT, blk, TG_SMEM>>>(yb, WoH, WoL, (float*)d_out, BT, HH, HH,
                                          nullptr, nullptr, nullptr);
}

// round 13
// speedup vs baseline: 1.0927x; 1.0927x over previous
#include <cuda_runtime.h>
#include <cuda_bf16.h>
#include <stdint.h>
#include <math.h>

// ---------------------------------------------------------------------------
// RWKV7 attention block, B=4 T=2048 H=1024 NH=16 HD=64.
// ALL GEMMs on mma.sync bf16 (hi+lo split, fp32 accum). Down-projections
// batched into one kernel. Sequential scan (per-step double buffer).
// ---------------------------------------------------------------------------

#define BB   4
#define TT   2048
#define HH   1024
#define HDD  64
#define NHH  16
#define BT   (BB*TT)        // 8192 tokens
#define BTH  (BT*HH)        // 8388608
#define DECAY_LOG_SCALE (-0.6065306597126334f)
#define GN_EPS (64.0f*1e-5f)

// ----------------------------- scratch ------------------------------------
static __device__ float g_xr[BTH], g_xw[BTH], g_xk[BTH], g_xv[BTH], g_xa[BTH], g_xg[BTH];
static __device__ float g_r[BTH], g_ew[BTH], g_k[BTH], g_v0[BTH], g_v[BTH], g_a[BTH];
static __device__ float g_an[BTH], g_bv[BTH], g_g[BTH], g_o[BTH], g_y[BTH];
static __device__ float g_t1[BT*64], g_t2[BT*64], g_t3[BT*64], g_t4[BT*160];

// transposed + bf16-split weights ([N,K] K-major)
static __device__ __nv_bfloat16 g_WrH[HH*HH], g_WrL[HH*HH];
static __device__ __nv_bfloat16 g_WkH[HH*HH], g_WkL[HH*HH];
static __device__ __nv_bfloat16 g_WvH[HH*HH], g_WvL[HH*HH];
static __device__ __nv_bfloat16 g_WoH[HH*HH], g_WoL[HH*HH];
static __device__ __nv_bfloat16 g_wBH[HH*64], g_wBL[HH*64];
static __device__ __nv_bfloat16 g_vBH[HH*64], g_vBL[HH*64];
static __device__ __nv_bfloat16 g_aBH[HH*64], g_aBL[HH*64];
static __device__ __nv_bfloat16 g_gBH[HH*160], g_gBL[HH*160];
// down-projection weights, transposed+split: (N, K=1024)
static __device__ __nv_bfloat16 g_wAH[64*HH], g_wAL[64*HH];
static __device__ __nv_bfloat16 g_vAH[64*HH], g_vAL[64*HH];
static __device__ __nv_bfloat16 g_aAH[64*HH], g_aAL[64*HH];
static __device__ __nv_bfloat16 g_gAH[160*HH], g_gAL[160*HH];

__device__ __forceinline__ float sigf(float x) { return 1.0f / (1.0f + expf(-x)); }

__device__ __forceinline__ uint32_t pack_bf2(__nv_bfloat16 lo, __nv_bfloat16 hi) {
    return (uint32_t)__bfloat16_as_ushort(lo) | ((uint32_t)__bfloat16_as_ushort(hi) << 16);
}

__device__ __forceinline__ uint32_t smem_u32(const void* p) {
    uint32_t a;
    asm("{ .reg .u64 t; cvta.to.shared.u64 t, %1; cvt.u32.u64 %0, t; }" : "=r"(a) : "l"(p));
    return a;
}

__device__ __forceinline__ void ldsm4(uint32_t& r0, uint32_t& r1, uint32_t& r2, uint32_t& r3,
                                      uint32_t addr)
{
    asm volatile("ldmatrix.sync.aligned.m8n8.x4.shared.b16 {%0,%1,%2,%3}, [%4];"
                 : "=r"(r0), "=r"(r1), "=r"(r2), "=r"(r3) : "r"(addr));
}

__device__ __forceinline__ void mma16816(float* c,
                                         uint32_t a0, uint32_t a1, uint32_t a2, uint32_t a3,
                                         uint32_t b0, uint32_t b1)
{
    asm volatile("mma.sync.aligned.m16n8k16.row.col.f32.bf16.bf16.f32 "
                 "{%0,%1,%2,%3}, {%4,%5,%6,%7}, {%8,%9}, {%0,%1,%2,%3};"
                 : "+f"(c[0]), "+f"(c[1]), "+f"(c[2]), "+f"(c[3])
                 : "r"(a0), "r"(a1), "r"(a2), "r"(a3), "r"(b0), "r"(b1));
}

// ----------------------------- prep: token shift ---------------------------
__global__ void prep_kernel(const float* __restrict__ hs,
                            const float* __restrict__ mr, const float* __restrict__ mw,
                            const float* __restrict__ mk, const float* __restrict__ mv,
                            const float* __restrict__ ma, const float* __restrict__ mg)
{
    int i4 = blockIdx.x * blockDim.x + threadIdx.x;
    if (i4 >= BTH / 4) return;
    int i = i4 * 4;
    int t = (i / HH) % TT;
    int h = i % HH;
    float4 x = *(const float4*)(hs + i);
    float4 p = make_float4(0.f, 0.f, 0.f, 0.f);
    if (t > 0) p = *(const float4*)(hs + i - HH);
    float4 d = make_float4(p.x - x.x, p.y - x.y, p.z - x.z, p.w - x.w);
#define DOMIX(dst, mp) { float4 m4 = *(const float4*)((mp) + h); float4 o4; \
    o4.x = fmaf(d.x, m4.x, x.x); o4.y = fmaf(d.y, m4.y, x.y); \
    o4.z = fmaf(d.z, m4.z, x.z); o4.w = fmaf(d.w, m4.w, x.w); \
    *(float4*)((dst) + i) = o4; }
    DOMIX(g_xr, mr) DOMIX(g_xw, mw) DOMIX(g_xk, mk)
    DOMIX(g_xv, mv) DOMIX(g_xa, ma) DOMIX(g_xg, mg)
#undef DOMIX
}

// ----------------- weight transpose + bf16 hi/lo split (all-in-one) -------
// Source W is (SK rows, SN cols) fp32 row-major; output (SN rows, SK cols)
// bf16 hi/lo. One 32x32 tile per block, 1D grid decode over all 12 matrices.
__global__ void convw_all_kernel(const float* __restrict__ Wr, const float* __restrict__ Wk,
                                 const float* __restrict__ Wv, const float* __restrict__ Wo,
                                 const float* __restrict__ wB, const float* __restrict__ vB,
                                 const float* __restrict__ aB, const float* __restrict__ gB,
                                 const float* __restrict__ wA, const float* __restrict__ vA,
                                 const float* __restrict__ aA, const float* __restrict__ gA)
{
    __shared__ float ts[32][33];
    int bidx = blockIdx.x;
    const float* W; __nv_bfloat16 *Bh, *Bl;
    int SK, SN, nb, kb;
    if (bidx < 4096) {                       // W_r/W_k/W_v/W_o (1024,1024)
        int m = bidx >> 10, local = bidx & 1023;
        SK = HH; SN = HH;
        nb = (local & 31) * 32; kb = (local >> 5) * 32;
        switch (m) {
            case 0: W = Wr; Bh = g_WrH; Bl = g_WrL; break;
            case 1: W = Wk; Bh = g_WkH; Bl = g_WkL; break;
            case 2: W = Wv; Bh = g_WvH; Bl = g_WvL; break;
            default: W = Wo; Bh = g_WoH; Bl = g_WoL; break;
        }
    } else if (bidx < 4288) {                // wB/vB/aB (64,1024)
        int m = (bidx - 4096) >> 6, local = (bidx - 4096) & 63;
        SK = 64; SN = HH;
        nb = (local & 31) * 32; kb = (local >> 5) * 32;
        switch (m) {
            case 0: W = wB; Bh = g_wBH; Bl = g_wBL; break;
            case 1: W = vB; Bh = g_vBH; Bl = g_vBL; break;
            default: W = aB; Bh = g_aBH; Bl = g_aBL; break;
        }
    } else if (bidx < 4448) {                // gB (160,1024)
        int local = bidx - 4288;
        SK = 160; SN = HH;
        nb = (local & 31) * 32; kb = (local >> 5) * 32;
        W = gB; Bh = g_gBH; Bl = g_gBL;
    } else if (bidx < 4640) {                // wA/vA/aA (1024,64)
        int m = (bidx - 4448) >> 6, local = (bidx - 4448) & 63;
        SK = HH; SN = 64;
        nb = (local & 1) * 32; kb = (local >> 1) * 32;
        switch (m) {
            case 0: W = wA; Bh = g_wAH; Bl = g_wAL; break;
            case 1: W = vA; Bh = g_vAH; Bl = g_vAL; break;
            default: W = aA; Bh = g_aAH; Bl = g_aAL; break;
        }
    } else {                                 // gA (1024,160)
        int local = bidx - 4640;
        SK = HH; SN = 160;
        nb = (local % 5) * 32; kb = (local / 5) * 32;
        W = gA; Bh = g_gAH; Bl = g_gAL;
    }
    int tx = threadIdx.x, ty = threadIdx.y;  // 32 x 8
    for (int i = ty; i < 32; i += 8)
        ts[i][tx] = W[(size_t)(kb + i) * SN + nb + tx];
    __syncthreads();
    for (int i = ty; i < 32; i += 8) {
        float x = ts[tx][i];                 // W[kb+tx][nb+i]
        __nv_bfloat16 h = __float2bfloat16(x);
        __nv_bfloat16 l = __float2bfloat16(x - __bfloat162float(h));
        size_t o = (size_t)(nb + i) * SK + kb + tx;
        Bh[o] = h; Bl[o] = l;
    }
}

// --------------------- mma.sync GEMM: C = A @ Bt^T -------------------------
// 128x128 CTA tile, BK=32, 8 warps (2x4), 3-product bf16 split.
#define LDS 40                       // padded row length (bf16 elems)
#define ABUF (128*LDS)
#define TG_SMEM (4*ABUF*2*2)         // 81920 B

template <int EPI>
__global__ void __launch_bounds__(256)
tgemm_kernel(const float* __restrict__ A,
             const __nv_bfloat16* __restrict__ Bh, const __nv_bfloat16* __restrict__ Bl,
             float* __restrict__ C, int M, int N, int K,
             const float* __restrict__ bias,
             const float* __restrict__ e0, const float* __restrict__ e1)
{
    extern __shared__ char smem[];
    __nv_bfloat16* As = (__nv_bfloat16*)smem;
    __nv_bfloat16* Bs = (__nv_bfloat16*)(smem + 2*2*ABUF*2);
    const int tid = threadIdx.x;
    const int wid = tid >> 5, lane = tid & 31;
    const int wm = wid >> 2, wn = wid & 3;
    const int m0 = blockIdx.y * 128, n0 = blockIdx.x * 128;

    float acc[4][4][4];
#pragma unroll
    for (int i = 0; i < 4; i++)
#pragma unroll
        for (int j = 0; j < 4; j++)
#pragma unroll
            for (int f = 0; f < 4; f++) acc[i][j][f] = 0.f;

    float4 aReg[4];
    uint4 bhReg[2], blReg[2];
    const int nC = K >> 5;

#define LOAD_REGS(kc) { \
        int k0 = (kc) << 5; \
        _Pragma("unroll") \
        for (int i = 0; i < 4; i++) { \
            int idx = tid + i * 256; \
            int r = idx >> 3, c4 = (idx & 7) << 2; \
            aReg[i] = *(const float4*)(A + (size_t)(m0 + r) * K + k0 + c4); \
        } \
        _Pragma("unroll") \
        for (int i = 0; i < 2; i++) { \
            int idx = tid + i * 256; \
            int r = idx >> 2, c8 = (idx & 3) << 3; \
            size_t go = (size_t)(n0 + r) * K + k0 + c8; \
            bhReg[i] = *(const uint4*)(Bh + go); \
            blReg[i] = *(const uint4*)(Bl + go); \
        } }

#define STORE_SMEM(b) { \
        __nv_bfloat16* aH = As + (b) * 2 * ABUF; \
        __nv_bfloat16* aL = aH + ABUF; \
        __nv_bfloat16* bH = Bs + (b) * 2 * ABUF; \
        __nv_bfloat16* bL = bH + ABUF; \
        _Pragma("unroll") \
        for (int i = 0; i < 4; i++) { \
            int idx = tid + i * 256; \
            int r = idx >> 3, c4 = (idx & 7) << 2; \
            float4 v = aReg[i]; \
            __nv_bfloat16 hx = __float2bfloat16(v.x); \
            __nv_bfloat16 hy = __float2bfloat16(v.y); \
            __nv_bfloat16 hz = __float2bfloat16(v.z); \
            __nv_bfloat16 hw = __float2bfloat16(v.w); \
            __nv_bfloat16 lx = __float2bfloat16(v.x - __bfloat162float(hx)); \
            __nv_bfloat16 ly = __float2bfloat16(v.y - __bfloat162float(hy)); \
            __nv_bfloat16 lz = __float2bfloat16(v.z - __bfloat162float(hz)); \
            __nv_bfloat16 lw = __float2bfloat16(v.w - __bfloat162float(hw)); \
            uint2 hv2, lv2; \
            hv2.x = pack_bf2(hx, hy); hv2.y = pack_bf2(hz, hw); \
            lv2.x = pack_bf2(lx, ly); lv2.y = pack_bf2(lz, lw); \
            *(uint2*)(aH + r * LDS + c4) = hv2; \
            *(uint2*)(aL + r * LDS + c4) = lv2; \
        } \
        _Pragma("unroll") \
        for (int i = 0; i < 2; i++) { \
            int idx = tid + i * 256; \
            int r = idx >> 2, c8 = (idx & 3) << 3; \
            *(uint4*)(bH + r * LDS + c8) = bhReg[i]; \
            *(uint4*)(bL + r * LDS + c8) = blReg[i]; \
        } }

    LOAD_REGS(0)
    STORE_SMEM(0)
    __syncthreads();

    for (int ic = 0; ic < nC; ic++) {
        int buf = ic & 1;
        if (ic + 1 < nC) LOAD_REGS(ic + 1)

        {
            uint32_t aBaseH = smem_u32(As + buf * 2 * ABUF);
            uint32_t aBaseL = aBaseH + ABUF * 2;
            uint32_t bBaseH = smem_u32(Bs + buf * 2 * ABUF);
            uint32_t bBaseL = bBaseH + ABUF * 2;
#pragma unroll
            for (int kk = 0; kk < 32; kk += 16) {
                uint32_t ah[4][4], al[4][4], bh[2][4], bl[2][4];
#pragma unroll
                for (int i = 0; i < 4; i++) {
                    int row = wm * 64 + i * 16 + (lane & 15);
                    int col = kk + ((lane >> 4) << 3);
                    uint32_t off = (uint32_t)(row * LDS + col) * 2;
                    ldsm4(ah[i][0], ah[i][1], ah[i][2], ah[i][3], aBaseH + off);
                    ldsm4(al[i][0], al[i][1], al[i][2], al[i][3], aBaseL + off);
                }
#pragma unroll
                for (int jp = 0; jp < 2; jp++) {
                    int row = wn * 32 + jp * 16 + ((lane >> 4) << 3) + (lane & 7);
                    int col = kk + ((lane >> 3) & 1) * 8;
                    uint32_t off = (uint32_t)(row * LDS + col) * 2;
                    ldsm4(bh[jp][0], bh[jp][1], bh[jp][2], bh[jp][3], bBaseH + off);
                    ldsm4(bl[jp][0], bl[jp][1], bl[jp][2], bl[jp][3], bBaseL + off);
                }
#pragma unroll
                for (int i = 0; i < 4; i++)
#pragma unroll
                    for (int j = 0; j < 4; j++) {
                        uint32_t b0h = bh[j >> 1][(j & 1) * 2], b1h = bh[j >> 1][(j & 1) * 2 + 1];
                        uint32_t b0l = bl[j >> 1][(j & 1) * 2], b1l = bl[j >> 1][(j & 1) * 2 + 1];
                        mma16816(acc[i][j], ah[i][0], ah[i][1], ah[i][2], ah[i][3], b0h, b1h);
                        mma16816(acc[i][j], ah[i][0], ah[i][1], ah[i][2], ah[i][3], b0l, b1l);
                        mma16816(acc[i][j], al[i][0], al[i][1], al[i][2], al[i][3], b0h, b1h);
                    }
            }
        }

        if (ic + 1 < nC) {
            __syncthreads();
            STORE_SMEM(buf ^ 1)
            __syncthreads();
        }
    }

    // ---- epilogue ----
    int g = lane >> 2, tig = lane & 3;
#pragma unroll
    for (int i = 0; i < 4; i++) {
        int r0 = m0 + wm * 64 + i * 16 + g;
#pragma unroll
        for (int j = 0; j < 4; j++) {
            int col = n0 + wn * 32 + j * 8 + tig * 2;
            float2 v0 = make_float2(acc[i][j][0], acc[i][j][1]);
            float2 v1 = make_float2(acc[i][j][2], acc[i][j][3]);
            if (EPI == 3 || EPI == 4 || EPI == 5) {
                float b0 = bias[col], b1 = bias[col + 1];
                v0.x = sigf(v0.x + b0); v0.y = sigf(v0.y + b1);
                v1.x = sigf(v1.x + b0); v1.y = sigf(v1.y + b1);
                if (EPI == 4) {
                    v0.x = expf(DECAY_LOG_SCALE * v0.x); v0.y = expf(DECAY_LOG_SCALE * v0.y);
                    v1.x = expf(DECAY_LOG_SCALE * v1.x); v1.y = expf(DECAY_LOG_SCALE * v1.y);
                } else if (EPI == 5) {
                    size_t o0 = (size_t)r0 * N + col, o1 = (size_t)(r0 + 8) * N + col;
                    float2 a0 = *(const float2*)(e0 + o0);
                    float2 c0v = *(const float2*)(e1 + o0);
                    float2 a1 = *(const float2*)(e0 + o1);
                    float2 c1v = *(const float2*)(e1 + o1);
                    v0.x = fmaf(v0.x, c0v.x - a0.x, a0.x);
                    v0.y = fmaf(v0.y, c0v.y - a0.y, a0.y);
                    v1.x = fmaf(v1.x, c1v.x - a1.x, a1.x);
                    v1.y = fmaf(v1.y, c1v.y - a1.y, a1.y);
                }
            }
            *(float2*)(C + (size_t)r0 * N + col) = v0;
            *(float2*)(C + (size_t)(r0 + 8) * N + col) = v1;
        }
    }
}

// ------------- batched down-projection GEMM (mma, 128x64 tiles) ------------
// grid (6, 64): tile 0: xw@wA->tanh->t1; 1: xv@vA->t2; 2: xa@aA->t3;
// 3..5: xg@gA->sigmoid->t4 (N=160, last tile guarded).
// Warps: 4(M) x 2(N); warp tile 32x32. acc[2][4][4].
#define DBBUF (64*LDS)
#define DG_SMEM (2*2*(ABUF+DBBUF)*2)   // 61440 B

__global__ void __launch_bounds__(256)
dgemm_kernel()
{
    extern __shared__ char smem[];
    __nv_bfloat16* As = (__nv_bfloat16*)smem;                  // [2][2][128][LDS]
    __nv_bfloat16* Bs = (__nv_bfloat16*)(smem + 2*2*ABUF*2);   // [2][2][64][LDS]
    const int tid = threadIdx.x;
    const int wid = tid >> 5, lane = tid & 31;
    const int wm = wid & 3, wn = wid >> 2 & 1;
    const int m0 = blockIdx.y * 128;
    const int tix = blockIdx.x;

    const float* A; const __nv_bfloat16 *BH, *BL; float* C;
    int Nseg, n0, epi;   // epi: 0 none, 1 tanh, 2 sigmoid
    if (tix == 0)      { A = g_xw; BH = g_wAH; BL = g_wAL; C = g_t1; Nseg = 64;  n0 = 0; epi = 1; }
    else if (tix == 1) { A = g_xv; BH = g_vAH; BL = g_vAL; C = g_t2; Nseg = 64;  n0 = 0; epi = 0; }
    else if (tix == 2) { A = g_xa; BH = g_aAH; BL = g_aAL; C = g_t3; Nseg = 64;  n0 = 0; epi = 0; }
    else               { A = g_xg; BH = g_gAH; BL = g_gAL; C = g_t4; Nseg = 160; n0 = (tix - 3) * 64; epi = 2; }

    const int K = HH;
    float acc[2][4][4];
#pragma unroll
    for (int i = 0; i < 2; i++)
#pragma unroll
        for (int j = 0; j < 4; j++)
#pragma unroll
            for (int f = 0; f < 4; f++) acc[i][j][f] = 0.f;

    float4 aReg[4];
    uint4 bhReg, blReg;
    const int nC = K >> 5;          // 32 chunks

    // B row handled by this thread (64 rows x 32 cols per chunk, 1 uint4 each)
    const int brow = tid >> 2, bc8 = (tid & 3) << 3;
    const bool bvalid = (n0 + brow) < Nseg;

#define D_LOAD(kc) { \
        int k0 = (kc) << 5; \
        _Pragma("unroll") \
        for (int i = 0; i < 4; i++) { \
            int idx = tid + i * 256; \
            int r = idx >> 3, c4 = (idx & 7) << 2; \
            aReg[i] = *(const float4*)(A + (size_t)(m0 + r) * K + k0 + c4); \
        } \
        if (bvalid) { \
            size_t go = (size_t)(n0 + brow) * K + k0 + bc8; \
            bhReg = *(const uint4*)(BH + go); \
            blReg = *(const uint4*)(BL + go); \
        } else { \
            bhReg = make_uint4(0,0,0,0); blReg = make_uint4(0,0,0,0); \
        } }

#define D_STORE(b) { \
        __nv_bfloat16* aH = As + (b) * 2 * ABUF; \
        __nv_bfloat16* aL = aH + ABUF; \
        __nv_bfloat16* bH = Bs + (b) * 2 * DBBUF; \
        __nv_bfloat16* bL = bH + DBBUF; \
        _Pragma("unroll") \
        for (int i = 0; i < 4; i++) { \
            int idx = tid + i * 256; \
            int r = idx >> 3, c4 = (idx & 7) << 2; \
            float4 v = aReg[i]; \
            __nv_bfloat16 hx = __float2bfloat16(v.x); \
            __nv_bfloat16 hy = __float2bfloat16(v.y); \
            __nv_bfloat16 hz = __float2bfloat16(v.z); \
            __nv_bfloat16 hw = __float2bfloat16(v.w); \
            __nv_bfloat16 lx = __float2bfloat16(v.x - __bfloat162float(hx)); \
            __nv_bfloat16 ly = __float2bfloat16(v.y - __bfloat162float(hy)); \
            __nv_bfloat16 lz = __float2bfloat16(v.z - __bfloat162float(hz)); \
            __nv_bfloat16 lw = __float2bfloat16(v.w - __bfloat162float(hw)); \
            uint2 hv2, lv2; \
            hv2.x = pack_bf2(hx, hy); hv2.y = pack_bf2(hz, hw); \
            lv2.x = pack_bf2(lx, ly); lv2.y = pack_bf2(lz, lw); \
            *(uint2*)(aH + r * LDS + c4) = hv2; \
            *(uint2*)(aL + r * LDS + c4) = lv2; \
        } \
        *(uint4*)(bH + brow * LDS + bc8) = bhReg; \
        *(uint4*)(bL + brow * LDS + bc8) = blReg; }

    D_LOAD(0)
    D_STORE(0)
    __syncthreads();

    for (int ic = 0; ic < nC; ic++) {
        int buf = ic & 1;
        if (ic + 1 < nC) D_LOAD(ic + 1)

        {
            uint32_t aBaseH = smem_u32(As + buf * 2 * ABUF);
            uint32_t aBaseL = aBaseH + ABUF * 2;
            uint32_t bBaseH = smem_u32(Bs + buf * 2 * DBBUF);
            uint32_t bBaseL = bBaseH + DBBUF * 2;
#pragma unroll
            for (int kk = 0; kk < 32; kk += 16) {
                uint32_t ah[2][4], al[2][4], bh[2][4], bl[2][4];
#pragma unroll
                for (int i = 0; i < 2; i++) {
                    int row = wm * 32 + i * 16 + (lane & 15);
                    int col = kk + ((lane >> 4) << 3);
                    uint32_t off = (uint32_t)(row * LDS + col) * 2;
                    ldsm4(ah[i][0], ah[i][1], ah[i][2], ah[i][3], aBaseH + off);
                    ldsm4(al[i][0], al[i][1], al[i][2], al[i][3], aBaseL + off);
                }
#pragma unroll
                for (int jp = 0; jp < 2; jp++) {
                    int row = wn * 32 + jp * 16 + ((lane >> 4) << 3) + (lane & 7);
                    int col = kk + ((lane >> 3) & 1) * 8;
                    uint32_t off = (uint32_t)(row * LDS + col) * 2;
                    ldsm4(bh[jp][0], bh[jp][1], bh[jp][2], bh[jp][3], bBaseH + off);
                    ldsm4(bl[jp][0], bl[jp][1], bl[jp][2], bl[jp][3], bBaseL + off);
                }
#pragma unroll
                for (int i = 0; i < 2; i++)
#pragma unroll
                    for (int j = 0; j < 4; j++) {
                        uint32_t b0h = bh[j >> 1][(j & 1) * 2], b1h = bh[j >> 1][(j & 1) * 2 + 1];
                        uint32_t b0l = bl[j >> 1][(j & 1) * 2], b1l = bl[j >> 1][(j & 1) * 2 + 1];
                        mma16816(acc[i][j], ah[i][0], ah[i][1], ah[i][2], ah[i][3], b0h, b1h);
                        mma16816(acc[i][j], ah[i][0], ah[i][1], ah[i][2], ah[i][3], b0l, b1l);
                        mma16816(acc[i][j], al[i][0], al[i][1], al[i][2], al[i][3], b0h, b1h);
                    }
            }
        }

        if (ic + 1 < nC) {
            __syncthreads();
            D_STORE(buf ^ 1)
            __syncthreads();
        }
    }

    // ---- epilogue ----
    int g = lane >> 2, tig = lane & 3;
#pragma unroll
    for (int i = 0; i < 2; i++) {
        int r0 = m0 + wm * 32 + i * 16 + g;
#pragma unroll
        for (int j = 0; j < 4; j++) {
            int gcol = n0 + wn * 32 + j * 8 + tig * 2;
            if (gcol >= Nseg) continue;
            float2 v0 = make_float2(acc[i][j][0], acc[i][j][1]);
            float2 v1 = make_float2(acc[i][j][2], acc[i][j][3]);
            if (epi == 1) {
                v0.x = tanhf(v0.x); v0.y = tanhf(v0.y);
                v1.x = tanhf(v1.x); v1.y = tanhf(v1.y);
            } else if (epi == 2) {
                v0.x = sigf(v0.x); v0.y = sigf(v0.y);
                v1.x = sigf(v1.x); v1.y = sigf(v1.y);
            }
            *(float2*)(C + (size_t)r0 * Nseg + gcol) = v0;
            *(float2*)(C + (size_t)(r0 + 8) * Nseg + gcol) = v1;
        }
    }
}

// --------------------- postproj: kk-normalize, k scale, a/b vecs -----------
__global__ void postproj_kernel(const float* __restrict__ kkw,
                                const float* __restrict__ kaw)
{
    int bt = blockIdx.x;
    int h = threadIdx.x;
    int head = h >> 6;
    int idx = bt * HH + h;
    float kv = g_k[idx], av = g_a[idx];
    float kkx = kv * kkw[h];
    float ss = kkx * kkx;
#pragma unroll
    for (int m = 16; m >= 1; m >>= 1) ss += __shfl_xor_sync(~0u, ss, m);
    __shared__ float ws[32];
    if ((h & 31) == 0) ws[h >> 5] = ss;
    __syncthreads();
    float tot = ws[head * 2] + ws[head * 2 + 1];
    float inv = 1.0f / fmaxf(sqrtf(tot), 1e-12f);
    float kkn = kkx * inv;
    g_an[idx] = -kkn;
    g_bv[idx] = kkn * av;
    g_k[idx] = kv * (1.0f + (av - 1.0f) * kaw[h]);
}

// ----------------------------- sequential scan (R10 version) ----------------
__global__ void __launch_bounds__(256) scan_kernel()
{
    __shared__ float sh[2][6][64];
    int pair = blockIdx.x >> 1;
    int rsplit = blockIdx.x & 1;
    int tid = threadIdx.x;
    int vloc = tid >> 3;
    int q = tid & 7;
    int vrow = rsplit * 32 + vloc;
    int b = pair >> 4, h = pair & 15;
    int base0 = b * TT * HH + h * HDD;

    const float* lp = nullptr;
    float* sd0 = nullptr; float* sd1 = nullptr;
    if (tid < 96) {
        int aid = tid >> 4, wq = tid & 15;
        switch (aid) {
            case 0: lp = g_r;  break;
            case 1: lp = g_ew; break;
            case 2: lp = g_k;  break;
            case 3: lp = g_v;  break;
            case 4: lp = g_an; break;
            default: lp = g_bv; break;
        }
        lp += base0 + (wq << 2);
        sd0 = &sh[0][aid][wq << 2];
        sd1 = &sh[1][aid][wq << 2];
    }

    float S[8];
#pragma unroll
    for (int j = 0; j < 8; j++) S[j] = 0.f;

    if (tid < 96) *(float4*)sd0 = *(const float4*)lp;
    __syncthreads();

    for (int t = 0; t < TT; t++) {
        int cur = t & 1;
        if (tid < 96 && t + 1 < TT) {
            float4 tmp = *(const float4*)(lp + (size_t)(t + 1) * HH);
            *(float4*)(cur ? sd0 : sd1) = tmp;
        }
        const float (*cs)[64] = sh[cur];
        int c0 = q << 3;

        float4 aA = *(const float4*)&cs[4][c0];
        float4 aB = *(const float4*)&cs[4][c0 + 4];
        float sa = S[0]*aA.x + S[1]*aA.y + S[2]*aA.z + S[3]*aA.w
                 + S[4]*aB.x + S[5]*aB.y + S[6]*aB.z + S[7]*aB.w;
        sa += __shfl_xor_sync(~0u, sa, 1);
        sa += __shfl_xor_sync(~0u, sa, 2);
        sa += __shfl_xor_sync(~0u, sa, 4);

        float vv = cs[3][vrow];
        float4 eA = *(const float4*)&cs[1][c0];
        float4 eB = *(const float4*)&cs[1][c0 + 4];
        float4 kA = *(const float4*)&cs[2][c0];
        float4 kB = *(const float4*)&cs[2][c0 + 4];
        float4 bA = *(const float4*)&cs[5][c0];
        float4 bB = *(const float4*)&cs[5][c0 + 4];

        S[0] = fmaf(S[0], eA.x, fmaf(sa, bA.x, vv * kA.x));
        S[1] = fmaf(S[1], eA.y, fmaf(sa, bA.y, vv * kA.y));
        S[2] = fmaf(S[2], eA.z, fmaf(sa, bA.z, vv * kA.z));
        S[3] = fmaf(S[3], eA.w, fmaf(sa, bA.w, vv * kA.w));
        S[4] = fmaf(S[4], eB.x, fmaf(sa, bB.x, vv * kB.x));
        S[5] = fmaf(S[5], eB.y, fmaf(sa, bB.y, vv * kB.y));
        S[6] = fmaf(S[6], eB.z, fmaf(sa, bB.z, vv * kB.z));
        S[7] = fmaf(S[7], eB.w, fmaf(sa, bB.w, vv * kB.w));

        float4 rA = *(const float4*)&cs[0][c0];
        float4 rB = *(const float4*)&cs[0][c0 + 4];
        float oo = S[0]*rA.x + S[1]*rA.y + S[2]*rA.z + S[3]*rA.w
                 + S[4]*rB.x + S[5]*rB.y + S[6]*rB.z + S[7]*rB.w;
        oo += __shfl_xor_sync(~0u, oo, 1);
        oo += __shfl_xor_sync(~0u, oo, 2);
        oo += __shfl_xor_sync(~0u, oo, 4);
        if (q == 0) g_o[base0 + t * HH + vrow] = oo;
        __syncthreads();
    }
}

// ---------------- groupnorm + bonus-corr + gate -> y ------------------------
__global__ void finalmix_kernel(const float* __restrict__ rkw,
                                const float* __restrict__ gnw,
                                const float* __restrict__ gnb)
{
    int bt = blockIdx.x;
    int head = threadIdx.x >> 5;
    int ld = threadIdx.x & 31;
    int base = bt * HH + head * HDD;
    int i0 = base + ld, i1 = base + 32 + ld;
    float o0 = g_o[i0], o1 = g_o[i1];
    float r0 = g_r[i0], r1 = g_r[i1];
    float k0 = g_k[i0], k1 = g_k[i1];
    float v0 = g_v[i0], v1 = g_v[i1];
    int h0 = head * HDD + ld, h1 = h0 + 32;

    float s  = o0 + o1;
    float qq = o0 * o0 + o1 * o1;
    float rk = r0 * k0 * rkw[h0] + r1 * k1 * rkw[h1];
#pragma unroll
    for (int m = 16; m >= 1; m >>= 1) {
        s  += __shfl_xor_sync(~0u, s,  m);
        qq += __shfl_xor_sync(~0u, qq, m);
        rk += __shfl_xor_sync(~0u, rk, m);
    }
    float mu = s * (1.0f / 64.0f);
    float var = qq * (1.0f / 64.0f) - mu * mu;
    float is = rsqrtf(var + GN_EPS);
    float y0 = (fmaf((o0 - mu) * is, gnw[h0], gnb[h0]) + rk * v0) * g_g[i0];
    float y1 = (fmaf((o1 - mu) * is, gnw[h1], gnb[h1]) + rk * v1) * g_g[i1];
    g_y[i0] = y0;
    g_y[i1] = y1;
}

// ----------------------------- host ----------------------------------------
extern "C" void kernel_launch(void* const* d_in, const int* in_sizes, int n_in,
                              void* d_out, int out_size)
{
    const float* hs  = (const float*)d_in[0];
    const float* vfi = (const float*)d_in[1];
    const float* x_r = (const float*)d_in[2];
    const float* x_w = (const float*)d_in[3];
    const float* x_k = (const float*)d_in[4];
    const float* x_v = (const float*)d_in[5];
    const float* x_a = (const float*)d_in[6];
    const float* x_g = (const float*)d_in[7];
    const float* k_k = (const float*)d_in[8];
    const float* k_a = (const float*)d_in[9];
    const float* r_k = (const float*)d_in[10];
    const float* W_r = (const float*)d_in[11];
    const float* W_k = (const float*)d_in[12];
    const float* W_v = (const float*)d_in[13];
    const float* W_o = (const float*)d_in[14];
    const float* wA  = (const float*)d_in[15];
    const float* wB  = (const float*)d_in[16];
    const float* wb  = (const float*)d_in[17];
    const float* vA  = (const float*)d_in[18];
    const float* vB  = (const float*)d_in[19];
    const float* vb  = (const float*)d_in[20];
    const float* aA  = (const float*)d_in[21];
    const float* aB  = (const float*)d_in[22];
    const float* ab  = (const float*)d_in[23];
    const float* gA  = (const float*)d_in[24];
    const float* gB  = (const float*)d_in[25];
    const float* gnw = (const float*)d_in[26];
    const float* gnb = (const float*)d_in[27];

    float *xr, *xk, *xv, *rb, *ewb, *kb, *v0b, *vb2, *ab2;
    float *t1, *t2, *t3, *t4, *gb2, *yb;
    cudaGetSymbolAddress((void**)&xr,  g_xr);
    cudaGetSymbolAddress((void**)&xk,  g_xk);
    cudaGetSymbolAddress((void**)&xv,  g_xv);
    cudaGetSymbolAddress((void**)&rb,  g_r);
    cudaGetSymbolAddress((void**)&ewb, g_ew);
    cudaGetSymbolAddress((void**)&kb,  g_k);
    cudaGetSymbolAddress((void**)&v0b, g_v0);
    cudaGetSymbolAddress((void**)&vb2, g_v);
    cudaGetSymbolAddress((void**)&ab2, g_a);
    cudaGetSymbolAddress((void**)&t1,  g_t1);
    cudaGetSymbolAddress((void**)&t2,  g_t2);
    cudaGetSymbolAddress((void**)&t3,  g_t3);
    cudaGetSymbolAddress((void**)&t4,  g_t4);
    cudaGetSymbolAddress((void**)&gb2, g_g);
    cudaGetSymbolAddress((void**)&yb,  g_y);

    __nv_bfloat16 *WrH, *WrL, *WkH, *WkL, *WvH, *WvL, *WoH, *WoL;
    __nv_bfloat16 *wBH, *wBL, *vBH, *vBL, *aBH, *aBL, *gBH, *gBL;
    cudaGetSymbolAddress((void**)&WrH, g_WrH); cudaGetSymbolAddress((void**)&WrL, g_WrL);
    cudaGetSymbolAddress((void**)&WkH, g_WkH); cudaGetSymbolAddress((void**)&WkL, g_WkL);
    cudaGetSymbolAddress((void**)&WvH, g_WvH); cudaGetSymbolAddress((void**)&WvL, g_WvL);
    cudaGetSymbolAddress((void**)&WoH, g_WoH); cudaGetSymbolAddress((void**)&WoL, g_WoL);
    cudaGetSymbolAddress((void**)&wBH, g_wBH); cudaGetSymbolAddress((void**)&wBL, g_wBL);
    cudaGetSymbolAddress((void**)&vBH, g_vBH); cudaGetSymbolAddress((void**)&vBL, g_vBL);
    cudaGetSymbolAddress((void**)&aBH, g_aBH); cudaGetSymbolAddress((void**)&aBL, g_aBL);
    cudaGetSymbolAddress((void**)&gBH, g_gBH); cudaGetSymbolAddress((void**)&gBL, g_gBL);

    cudaFuncSetAttribute(tgemm_kernel<0>, cudaFuncAttributeMaxDynamicSharedMemorySize, TG_SMEM);
    cudaFuncSetAttribute(tgemm_kernel<3>, cudaFuncAttributeMaxDynamicSharedMemorySize, TG_SMEM);
    cudaFuncSetAttribute(tgemm_kernel<4>, cudaFuncAttributeMaxDynamicSharedMemorySize, TG_SMEM);
    cudaFuncSetAttribute(tgemm_kernel<5>, cudaFuncAttributeMaxDynamicSharedMemorySize, TG_SMEM);
    cudaFuncSetAttribute(dgemm_kernel,    cudaFuncAttributeMaxDynamicSharedMemorySize, DG_SMEM);

    dim3 blk(256);
    dim3 gT(HH / 128, BT / 128);       // 8 x 64 tiles
    dim3 gD(6, BT / 128);              // batched down-proj
    dim3 cblk(32, 8);

    // 0: all weight transposes + bf16 splits
    convw_all_kernel<<<4800, cblk>>>(W_r, W_k, W_v, W_o, wB, vB, aB, gB, wA, vA, aA, gA);

    // 1: token-shift mixes
    prep_kernel<<<BTH / 4 / 256, 256>>>(hs, x_r, x_w, x_k, x_v, x_a, x_g);

    // 2-4: big projections (capture slot lands here)
    tgemm_kernel<0><<<gT, blk, TG_SMEM>>>(xr, WrH, WrL, rb,  BT, HH, HH, nullptr, nullptr, nullptr);
    tgemm_kernel<0><<<gT, blk, TG_SMEM>>>(xk, WkH, WkL, kb,  BT, HH, HH, nullptr, nullptr, nullptr);
    tgemm_kernel<0><<<gT, blk, TG_SMEM>>>(xv, WvH, WvL, v0b, BT, HH, HH, nullptr, nullptr, nullptr);

    // 5: batched LoRA/gate down-projections (fused tanh/sigmoid)
    dgemm_kernel<<<gD, blk, DG_SMEM>>>();

    // 6-9: up-projections with fused epilogues
    tgemm_kernel<4><<<gT, blk, TG_SMEM>>>(t1, wBH, wBL, ewb, BT, HH, 64, wb, nullptr, nullptr);
    tgemm_kernel<5><<<gT, blk, TG_SMEM>>>(t2, vBH, vBL, vb2, BT, HH, 64, vb, v0b, vfi);
    tgemm_kernel<3><<<gT, blk, TG_SMEM>>>(t3, aBH, aBL, ab2, BT, HH, 64, ab, nullptr, nullptr);
    tgemm_kernel<0><<<gT, blk, TG_SMEM>>>(t4, gBH, gBL, gb2, BT, HH, 160, nullptr, nullptr, nullptr);

    // 10: kk normalize / k scale / scan coefficient vectors
    postproj_kernel<<<BT, 1024>>>(k_k, k_a);

    // 11: sequential RWKV7 scan
    scan_kernel<<<128, 256>>>();

    // 12: groupnorm + correction + gate
    finalmix_kernel<<<BT, 512>>>(r_k, gnw, gnb);

    // 13: output projection
    tgemm_kernel<0><<<gT, blk, TG_SMEM>>>(yb, WoH, WoL, (float*)d_out, BT, HH, HH,
                                          nullptr, nullptr, nullptr);
}

// round 14
// speedup vs baseline: 1.1788x; 1.0788x over previous
#include <cuda_runtime.h>
#include <cuda_bf16.h>
#include <stdint.h>
#include <math.h>

// ---------------------------------------------------------------------------
// RWKV7 attention block, B=4 T=2048 H=1024 NH=16 HD=64.
// All GEMMs: mma.sync bf16 hi/lo split, fp32 accum. GEMM inputs pre-split to
// bf16 hi/lo at their producers; GEMM staging is pure cp.async (no in-kernel
// conversion) -> low regs -> 2 CTAs/SM.
// ---------------------------------------------------------------------------

#define BB   4
#define TT   2048
#define HH   1024
#define HDD  64
#define NHH  16
#define BT   (BB*TT)        // 8192 tokens
#define BTH  (BT*HH)        // 8388608
#define DECAY_LOG_SCALE (-0.6065306597126334f)
#define GN_EPS (64.0f*1e-5f)

// ----------------------------- scratch ------------------------------------
// fp32 tensors consumed by non-GEMM stages
static __device__ float g_r[BTH], g_ew[BTH], g_k[BTH], g_v0[BTH], g_v[BTH], g_a[BTH];
static __device__ float g_an[BTH], g_bv[BTH], g_g[BTH], g_o[BTH];
// bf16 hi/lo pre-split GEMM inputs
static __device__ __nv_bfloat16 g_xrH[BTH], g_xrL[BTH], g_xwH[BTH], g_xwL[BTH];
static __device__ __nv_bfloat16 g_xkH[BTH], g_xkL[BTH], g_xvH[BTH], g_xvL[BTH];
static __device__ __nv_bfloat16 g_xaH[BTH], g_xaL[BTH], g_xgH[BTH], g_xgL[BTH];
static __device__ __nv_bfloat16 g_t1H[BT*64], g_t1L[BT*64], g_t2H[BT*64], g_t2L[BT*64];
static __device__ __nv_bfloat16 g_t3H[BT*64], g_t3L[BT*64], g_t4H[BT*160], g_t4L[BT*160];
static __device__ __nv_bfloat16 g_yH[BTH], g_yL[BTH];

// transposed + bf16-split weights ([N,K] K-major)
static __device__ __nv_bfloat16 g_WrH[HH*HH], g_WrL[HH*HH];
static __device__ __nv_bfloat16 g_WkH[HH*HH], g_WkL[HH*HH];
static __device__ __nv_bfloat16 g_WvH[HH*HH], g_WvL[HH*HH];
static __device__ __nv_bfloat16 g_WoH[HH*HH], g_WoL[HH*HH];
static __device__ __nv_bfloat16 g_wBH[HH*64], g_wBL[HH*64];
static __device__ __nv_bfloat16 g_vBH[HH*64], g_vBL[HH*64];
static __device__ __nv_bfloat16 g_aBH[HH*64], g_aBL[HH*64];
static __device__ __nv_bfloat16 g_gBH[HH*160], g_gBL[HH*160];
static __device__ __nv_bfloat16 g_wAH[64*HH], g_wAL[64*HH];
static __device__ __nv_bfloat16 g_vAH[64*HH], g_vAL[64*HH];
static __device__ __nv_bfloat16 g_aAH[64*HH], g_aAL[64*HH];
static __device__ __nv_bfloat16 g_gAH[160*HH], g_gAL[160*HH];

__device__ __forceinline__ float sigf(float x) { return 1.0f / (1.0f + expf(-x)); }

__device__ __forceinline__ uint32_t pack_bf2(__nv_bfloat16 lo, __nv_bfloat16 hi) {
    return (uint32_t)__bfloat16_as_ushort(lo) | ((uint32_t)__bfloat16_as_ushort(hi) << 16);
}

__device__ __forceinline__ uint32_t smem_u32(const void* p) {
    uint32_t a;
    asm("{ .reg .u64 t; cvta.to.shared.u64 t, %1; cvt.u32.u64 %0, t; }" : "=r"(a) : "l"(p));
    return a;
}

__device__ __forceinline__ void cpa16(uint32_t dst, const void* src) {
    asm volatile("cp.async.ca.shared.global [%0], [%1], 16;" :: "r"(dst), "l"(src));
}
#define CP_COMMIT() asm volatile("cp.async.commit_group;" ::: "memory")
#define CP_WAIT0()  asm volatile("cp.async.wait_group 0;" ::: "memory")

__device__ __forceinline__ void ldsm4(uint32_t& r0, uint32_t& r1, uint32_t& r2, uint32_t& r3,
                                      uint32_t addr)
{
    asm volatile("ldmatrix.sync.aligned.m8n8.x4.shared.b16 {%0,%1,%2,%3}, [%4];"
                 : "=r"(r0), "=r"(r1), "=r"(r2), "=r"(r3) : "r"(addr));
}

__device__ __forceinline__ void mma16816(float* c,
                                         uint32_t a0, uint32_t a1, uint32_t a2, uint32_t a3,
                                         uint32_t b0, uint32_t b1)
{
    asm volatile("mma.sync.aligned.m16n8k16.row.col.f32.bf16.bf16.f32 "
                 "{%0,%1,%2,%3}, {%4,%5,%6,%7}, {%8,%9}, {%0,%1,%2,%3};"
                 : "+f"(c[0]), "+f"(c[1]), "+f"(c[2]), "+f"(c[3])
                 : "r"(a0), "r"(a1), "r"(a2), "r"(a3), "r"(b0), "r"(b1));
}

// ----------------------------- prep: token shift -> bf16 hi/lo -------------
__global__ void prep_kernel(const float* __restrict__ hs,
                            const float* __restrict__ mr, const float* __restrict__ mw,
                            const float* __restrict__ mk, const float* __restrict__ mv,
                            const float* __restrict__ ma, const float* __restrict__ mg)
{
    int i4 = blockIdx.x * blockDim.x + threadIdx.x;
    if (i4 >= BTH / 4) return;
    int i = i4 * 4;
    int t = (i / HH) % TT;
    int h = i % HH;
    float4 x = *(const float4*)(hs + i);
    float4 p = make_float4(0.f, 0.f, 0.f, 0.f);
    if (t > 0) p = *(const float4*)(hs + i - HH);
    float4 d = make_float4(p.x - x.x, p.y - x.y, p.z - x.z, p.w - x.w);
#define DOMIX(dH, dL, mp) { \
    float4 m4 = *(const float4*)((mp) + h); float4 o4; \
    o4.x = fmaf(d.x, m4.x, x.x); o4.y = fmaf(d.y, m4.y, x.y); \
    o4.z = fmaf(d.z, m4.z, x.z); o4.w = fmaf(d.w, m4.w, x.w); \
    __nv_bfloat16 h0 = __float2bfloat16(o4.x), h1 = __float2bfloat16(o4.y); \
    __nv_bfloat16 h2 = __float2bfloat16(o4.z), h3 = __float2bfloat16(o4.w); \
    __nv_bfloat16 l0 = __float2bfloat16(o4.x - __bfloat162float(h0)); \
    __nv_bfloat16 l1 = __float2bfloat16(o4.y - __bfloat162float(h1)); \
    __nv_bfloat16 l2 = __float2bfloat16(o4.z - __bfloat162float(h2)); \
    __nv_bfloat16 l3 = __float2bfloat16(o4.w - __bfloat162float(h3)); \
    uint2 hv; hv.x = pack_bf2(h0, h1); hv.y = pack_bf2(h2, h3); \
    uint2 lv; lv.x = pack_bf2(l0, l1); lv.y = pack_bf2(l2, l3); \
    *(uint2*)((dH) + i) = hv; *(uint2*)((dL) + i) = lv; }
    DOMIX(g_xrH, g_xrL, mr) DOMIX(g_xwH, g_xwL, mw) DOMIX(g_xkH, g_xkL, mk)
    DOMIX(g_xvH, g_xvL, mv) DOMIX(g_xaH, g_xaL, ma) DOMIX(g_xgH, g_xgL, mg)
#undef DOMIX
}

// ----------------- weight transpose + bf16 hi/lo split (all-in-one) -------
__global__ void convw_all_kernel(const float* __restrict__ Wr, const float* __restrict__ Wk,
                                 const float* __restrict__ Wv, const float* __restrict__ Wo,
                                 const float* __restrict__ wB, const float* __restrict__ vB,
                                 const float* __restrict__ aB, const float* __restrict__ gB,
                                 const float* __restrict__ wA, const float* __restrict__ vA,
                                 const float* __restrict__ aA, const float* __restrict__ gA)
{
    __shared__ float ts[32][33];
    int bidx = blockIdx.x;
    const float* W; __nv_bfloat16 *Bh, *Bl;
    int SK, SN, nb, kb;
    if (bidx < 4096) {
        int m = bidx >> 10, local = bidx & 1023;
        SK = HH; SN = HH;
        nb = (local & 31) * 32; kb = (local >> 5) * 32;
        switch (m) {
            case 0: W = Wr; Bh = g_WrH; Bl = g_WrL; break;
            case 1: W = Wk; Bh = g_WkH; Bl = g_WkL; break;
            case 2: W = Wv; Bh = g_WvH; Bl = g_WvL; break;
            default: W = Wo; Bh = g_WoH; Bl = g_WoL; break;
        }
    } else if (bidx < 4288) {
        int m = (bidx - 4096) >> 6, local = (bidx - 4096) & 63;
        SK = 64; SN = HH;
        nb = (local & 31) * 32; kb = (local >> 5) * 32;
        switch (m) {
            case 0: W = wB; Bh = g_wBH; Bl = g_wBL; break;
            case 1: W = vB; Bh = g_vBH; Bl = g_vBL; break;
            default: W = aB; Bh = g_aBH; Bl = g_aBL; break;
        }
    } else if (bidx < 4448) {
        int local = bidx - 4288;
        SK = 160; SN = HH;
        nb = (local & 31) * 32; kb = (local >> 5) * 32;
        W = gB; Bh = g_gBH; Bl = g_gBL;
    } else if (bidx < 4640) {
        int m = (bidx - 4448) >> 6, local = (bidx - 4448) & 63;
        SK = HH; SN = 64;
        nb = (local & 1) * 32; kb = (local >> 1) * 32;
        switch (m) {
            case 0: W = wA; Bh = g_wAH; Bl = g_wAL; break;
            case 1: W = vA; Bh = g_vAH; Bl = g_vAL; break;
            default: W = aA; Bh = g_aAH; Bl = g_aAL; break;
        }
    } else {
        int local = bidx - 4640;
        SK = HH; SN = 160;
        nb = (local % 5) * 32; kb = (local / 5) * 32;
        W = gA; Bh = g_gAH; Bl = g_gAL;
    }
    int tx = threadIdx.x, ty = threadIdx.y;  // 32 x 8
    for (int i = ty; i < 32; i += 8)
        ts[i][tx] = W[(size_t)(kb + i) * SN + nb + tx];
    __syncthreads();
    for (int i = ty; i < 32; i += 8) {
        float x = ts[tx][i];
        __nv_bfloat16 h = __float2bfloat16(x);
        __nv_bfloat16 l = __float2bfloat16(x - __bfloat162float(h));
        size_t o = (size_t)(nb + i) * SK + kb + tx;
        Bh[o] = h; Bl[o] = l;
    }
}

// --------------------- mma.sync GEMM: C = A @ Bt^T -------------------------
// A, Bt both pre-split bf16 hi/lo, (M,K)/(N,K) K-major. cp.async staging.
// 128x128 CTA tile, BK=32, 8 warps (2x4). 3-product split.
#define LDS 40                       // padded row length (bf16 elems); 80B, 16B-mult
#define ABUF (128*LDS)               // elems per matrix tile
#define TG_SMEM (8*ABUF*2)           // 2 bufs x (Ahi+Alo+Bhi+Blo) = 81920 B

template <int EPI>
__global__ void __launch_bounds__(256, 2)
tgemm_kernel(const __nv_bfloat16* __restrict__ Ah, const __nv_bfloat16* __restrict__ Al,
             const __nv_bfloat16* __restrict__ Bh, const __nv_bfloat16* __restrict__ Bl,
             float* __restrict__ C, int M, int N, int K,
             const float* __restrict__ bias,
             const float* __restrict__ e0, const float* __restrict__ e1)
{
    extern __shared__ char smem[];
    const uint32_t sA = smem_u32(smem);                 // A: 2 bufs x 2 x ABUF
    const uint32_t sB = sA + 4 * ABUF * 2;              // B region
    const int tid = threadIdx.x;
    const int wid = tid >> 5, lane = tid & 31;
    const int wm = wid >> 2, wn = wid & 3;
    const int m0 = blockIdx.y * 128, n0 = blockIdx.x * 128;

    float acc[4][4][4];
#pragma unroll
    for (int i = 0; i < 4; i++)
#pragma unroll
        for (int j = 0; j < 4; j++)
#pragma unroll
            for (int f = 0; f < 4; f++) acc[i][j][f] = 0.f;

    const int nC = K >> 5;

#define T_LOAD(kc, b) { \
        int k0 = (kc) << 5; \
        uint32_t aH = sA + (b) * (4 * ABUF); \
        uint32_t bH = sB + (b) * (4 * ABUF); \
        _Pragma("unroll") \
        for (int i = 0; i < 2; i++) { \
            int idx = tid + i * 256; \
            int r = idx >> 2, c = (idx & 3) << 3; \
            uint32_t so = (uint32_t)(r * LDS + c) * 2; \
            size_t ga = (size_t)(m0 + r) * K + k0 + c; \
            size_t gb = (size_t)(n0 + r) * K + k0 + c; \
            cpa16(aH + so, Ah + ga); \
            cpa16(aH + 2 * ABUF + so, Al + ga); \
            cpa16(bH + so, Bh + gb); \
            cpa16(bH + 2 * ABUF + so, Bl + gb); \
        } }

    T_LOAD(0, 0)
    CP_COMMIT();
    CP_WAIT0();
    __syncthreads();

    for (int ic = 0; ic < nC; ic++) {
        int buf = ic & 1;
        if (ic + 1 < nC) { T_LOAD(ic + 1, buf ^ 1) CP_COMMIT(); }

        {
            uint32_t aBaseH = sA + buf * (4 * ABUF);
            uint32_t aBaseL = aBaseH + 2 * ABUF;
            uint32_t bBaseH = sB + buf * (4 * ABUF);
            uint32_t bBaseL = bBaseH + 2 * ABUF;
#pragma unroll
            for (int kk = 0; kk < 32; kk += 16) {
                uint32_t ah[4][4], al[4][4], bh[2][4], bl[2][4];
#pragma unroll
                for (int i = 0; i < 4; i++) {
                    int row = wm * 64 + i * 16 + (lane & 15);
                    int col = kk + ((lane >> 4) << 3);
                    uint32_t off = (uint32_t)(row * LDS + col) * 2;
                    ldsm4(ah[i][0], ah[i][1], ah[i][2], ah[i][3], aBaseH + off);
                    ldsm4(al[i][0], al[i][1], al[i][2], al[i][3], aBaseL + off);
                }
#pragma unroll
                for (int jp = 0; jp < 2; jp++) {
                    int row = wn * 32 + jp * 16 + ((lane >> 4) << 3) + (lane & 7);
                    int col = kk + ((lane >> 3) & 1) * 8;
                    uint32_t off = (uint32_t)(row * LDS + col) * 2;
                    ldsm4(bh[jp][0], bh[jp][1], bh[jp][2], bh[jp][3], bBaseH + off);
                    ldsm4(bl[jp][0], bl[jp][1], bl[jp][2], bl[jp][3], bBaseL + off);
                }
#pragma unroll
                for (int i = 0; i < 4; i++)
#pragma unroll
                    for (int j = 0; j < 4; j++) {
                        uint32_t b0h = bh[j >> 1][(j & 1) * 2], b1h = bh[j >> 1][(j & 1) * 2 + 1];
                        uint32_t b0l = bl[j >> 1][(j & 1) * 2], b1l = bl[j >> 1][(j & 1) * 2 + 1];
                        mma16816(acc[i][j], ah[i][0], ah[i][1], ah[i][2], ah[i][3], b0h, b1h);
                        mma16816(acc[i][j], ah[i][0], ah[i][1], ah[i][2], ah[i][3], b0l, b1l);
                        mma16816(acc[i][j], al[i][0], al[i][1], al[i][2], al[i][3], b0h, b1h);
                    }
            }
        }

        if (ic + 1 < nC) {
            CP_WAIT0();
            __syncthreads();
        }
    }

    // ---- epilogue ----
    int g = lane >> 2, tig = lane & 3;
#pragma unroll
    for (int i = 0; i < 4; i++) {
        int r0 = m0 + wm * 64 + i * 16 + g;
#pragma unroll
        for (int j = 0; j < 4; j++) {
            int col = n0 + wn * 32 + j * 8 + tig * 2;
            float2 v0 = make_float2(acc[i][j][0], acc[i][j][1]);
            float2 v1 = make_float2(acc[i][j][2], acc[i][j][3]);
            if (EPI == 3 || EPI == 4 || EPI == 5) {
                float b0 = bias[col], b1 = bias[col + 1];
                v0.x = sigf(v0.x + b0); v0.y = sigf(v0.y + b1);
                v1.x = sigf(v1.x + b0); v1.y = sigf(v1.y + b1);
                if (EPI == 4) {
                    v0.x = expf(DECAY_LOG_SCALE * v0.x); v0.y = expf(DECAY_LOG_SCALE * v0.y);
                    v1.x = expf(DECAY_LOG_SCALE * v1.x); v1.y = expf(DECAY_LOG_SCALE * v1.y);
                } else if (EPI == 5) {
                    size_t o0 = (size_t)r0 * N + col, o1 = (size_t)(r0 + 8) * N + col;
                    float2 a0 = *(const float2*)(e0 + o0);
                    float2 c0v = *(const float2*)(e1 + o0);
                    float2 a1 = *(const float2*)(e0 + o1);
                    float2 c1v = *(const float2*)(e1 + o1);
                    v0.x = fmaf(v0.x, c0v.x - a0.x, a0.x);
                    v0.y = fmaf(v0.y, c0v.y - a0.y, a0.y);
                    v1.x = fmaf(v1.x, c1v.x - a1.x, a1.x);
                    v1.y = fmaf(v1.y, c1v.y - a1.y, a1.y);
                }
            }
            *(float2*)(C + (size_t)r0 * N + col) = v0;
            *(float2*)(C + (size_t)(r0 + 8) * N + col) = v1;
        }
    }
}

// ------------- batched down-projection GEMM (mma, 128x64 tiles) ------------
// outputs written as bf16 hi/lo pairs.
#define DBBUF (64*LDS)
#define DG_SMEM ((4*ABUF + 4*DBBUF)*2)   // 61440 B

__global__ void __launch_bounds__(256, 2)
dgemm_kernel()
{
    extern __shared__ char smem[];
    const uint32_t sA = smem_u32(smem);
    const uint32_t sB = sA + 4 * ABUF * 2;
    const int tid = threadIdx.x;
    const int wid = tid >> 5, lane = tid & 31;
    const int wm = wid & 3, wn = (wid >> 2) & 1;
    const int m0 = blockIdx.y * 128;
    const int tix = blockIdx.x;

    const __nv_bfloat16 *Ah, *Al, *BH, *BL;
    __nv_bfloat16 *CH, *CL;
    int Nseg, n0, epi;
    if (tix == 0)      { Ah = g_xwH; Al = g_xwL; BH = g_wAH; BL = g_wAL; CH = g_t1H; CL = g_t1L; Nseg = 64;  n0 = 0; epi = 1; }
    else if (tix == 1) { Ah = g_xvH; Al = g_xvL; BH = g_vAH; BL = g_vAL; CH = g_t2H; CL = g_t2L; Nseg = 64;  n0 = 0; epi = 0; }
    else if (tix == 2) { Ah = g_xaH; Al = g_xaL; BH = g_aAH; BL = g_aAL; CH = g_t3H; CL = g_t3L; Nseg = 64;  n0 = 0; epi = 0; }
    else               { Ah = g_xgH; Al = g_xgL; BH = g_gAH; BL = g_gAL; CH = g_t4H; CL = g_t4L; Nseg = 160; n0 = (tix - 3) * 64; epi = 2; }

    const int K = HH;
    float acc[2][4][4];
#pragma unroll
    for (int i = 0; i < 2; i++)
#pragma unroll
        for (int j = 0; j < 4; j++)
#pragma unroll
            for (int f = 0; f < 4; f++) acc[i][j][f] = 0.f;

    const int nC = K >> 5;
    const int brow = tid >> 2, bc = (tid & 3) << 3;
    const bool bvalid = (n0 + brow) < Nseg;

    // zero B smem rows that are OOB (done once; cp.async skips them)
    if (!bvalid) {
#pragma unroll
        for (int b = 0; b < 2; b++) {
            uint32_t bH = sB + b * (4 * DBBUF);
            uint32_t so = (uint32_t)(brow * LDS + bc) * 2;
            *(uint4*)(smem + (bH - sA) + so) = make_uint4(0, 0, 0, 0);
            *(uint4*)(smem + (bH + 2 * DBBUF - sA) + so) = make_uint4(0, 0, 0, 0);
        }
    }
    __syncthreads();

#define D_LOAD(kc, b) { \
        int k0 = (kc) << 5; \
        uint32_t aH = sA + (b) * (4 * ABUF); \
        uint32_t bH = sB + (b) * (4 * DBBUF); \
        _Pragma("unroll") \
        for (int i = 0; i < 2; i++) { \
            int idx = tid + i * 256; \
            int r = idx >> 2, c = (idx & 3) << 3; \
            uint32_t so = (uint32_t)(r * LDS + c) * 2; \
            size_t ga = (size_t)(m0 + r) * K + k0 + c; \
            cpa16(aH + so, Ah + ga); \
            cpa16(aH + 2 * ABUF + so, Al + ga); \
        } \
        if (bvalid) { \
            uint32_t so = (uint32_t)(brow * LDS + bc) * 2; \
            size_t gb = (size_t)(n0 + brow) * K + k0 + bc; \
            cpa16(bH + so, BH + gb); \
            cpa16(bH + 2 * DBBUF + so, BL + gb); \
        } }

    D_LOAD(0, 0)
    CP_COMMIT();
    CP_WAIT0();
    __syncthreads();

    for (int ic = 0; ic < nC; ic++) {
        int buf = ic & 1;
        if (ic + 1 < nC) { D_LOAD(ic + 1, buf ^ 1) CP_COMMIT(); }

        {
            uint32_t aBaseH = sA + buf * (4 * ABUF);
            uint32_t aBaseL = aBaseH + 2 * ABUF;
            uint32_t bBaseH = sB + buf * (4 * DBBUF);
            uint32_t bBaseL = bBaseH + 2 * DBBUF;
#pragma unroll
            for (int kk = 0; kk < 32; kk += 16) {
                uint32_t ah[2][4], al[2][4], bh[2][4], bl[2][4];
#pragma unroll
                for (int i = 0; i < 2; i++) {
                    int row = wm * 32 + i * 16 + (lane & 15);
                    int col = kk + ((lane >> 4) << 3);
                    uint32_t off = (uint32_t)(row * LDS + col) * 2;
                    ldsm4(ah[i][0], ah[i][1], ah[i][2], ah[i][3], aBaseH + off);
                    ldsm4(al[i][0], al[i][1], al[i][2], al[i][3], aBaseL + off);
                }
#pragma unroll
                for (int jp = 0; jp < 2; jp++) {
                    int row = wn * 32 + jp * 16 + ((lane >> 4) << 3) + (lane & 7);
                    int col = kk + ((lane >> 3) & 1) * 8;
                    uint32_t off = (uint32_t)(row * LDS + col) * 2;
                    ldsm4(bh[jp][0], bh[jp][1], bh[jp][2], bh[jp][3], bBaseH + off);
                    ldsm4(bl[jp][0], bl[jp][1], bl[jp][2], bl[jp][3], bBaseL + off);
                }
#pragma unroll
                for (int i = 0; i < 2; i++)
#pragma unroll
                    for (int j = 0; j < 4; j++) {
                        uint32_t b0h = bh[j >> 1][(j & 1) * 2], b1h = bh[j >> 1][(j & 1) * 2 + 1];
                        uint32_t b0l = bl[j >> 1][(j & 1) * 2], b1l = bl[j >> 1][(j & 1) * 2 + 1];
                        mma16816(acc[i][j], ah[i][0], ah[i][1], ah[i][2], ah[i][3], b0h, b1h);
                        mma16816(acc[i][j], ah[i][0], ah[i][1], ah[i][2], ah[i][3], b0l, b1l);
                        mma16816(acc[i][j], al[i][0], al[i][1], al[i][2], al[i][3], b0h, b1h);
                    }
            }
        }

        if (ic + 1 < nC) {
            CP_WAIT0();
            __syncthreads();
        }
    }

    // ---- epilogue: activation + bf16 hi/lo store ----
    int g = lane >> 2, tig = lane & 3;
#pragma unroll
    for (int i = 0; i < 2; i++) {
        int r0 = m0 + wm * 32 + i * 16 + g;
#pragma unroll
        for (int j = 0; j < 4; j++) {
            int gcol = n0 + wn * 32 + j * 8 + tig * 2;
            if (gcol >= Nseg) continue;
            float2 v0 = make_float2(acc[i][j][0], acc[i][j][1]);
            float2 v1 = make_float2(acc[i][j][2], acc[i][j][3]);
            if (epi == 1) {
                v0.x = tanhf(v0.x); v0.y = tanhf(v0.y);
                v1.x = tanhf(v1.x); v1.y = tanhf(v1.y);
            } else if (epi == 2) {
                v0.x = sigf(v0.x); v0.y = sigf(v0.y);
                v1.x = sigf(v1.x); v1.y = sigf(v1.y);
            }
#define STORE_HL(val2, roff) { \
            __nv_bfloat16 h0 = __float2bfloat16((val2).x), h1 = __float2bfloat16((val2).y); \
            __nv_bfloat16 l0 = __float2bfloat16((val2).x - __bfloat162float(h0)); \
            __nv_bfloat16 l1 = __float2bfloat16((val2).y - __bfloat162float(h1)); \
            size_t oo = (size_t)(roff) * Nseg + gcol; \
            *(uint32_t*)(CH + oo) = pack_bf2(h0, h1); \
            *(uint32_t*)(CL + oo) = pack_bf2(l0, l1); }
            STORE_HL(v0, r0)
            STORE_HL(v1, r0 + 8)
#undef STORE_HL
        }
    }
}

// --------------------- postproj: kk-normalize, k scale, a/b vecs -----------
__global__ void postproj_kernel(const float* __restrict__ kkw,
                                const float* __restrict__ kaw)
{
    int bt = blockIdx.x;
    int h = threadIdx.x;
    int head = h >> 6;
    int idx = bt * HH + h;
    float kv = g_k[idx], av = g_a[idx];
    float kkx = kv * kkw[h];
    float ss = kkx * kkx;
#pragma unroll
    for (int m = 16; m >= 1; m >>= 1) ss += __shfl_xor_sync(~0u, ss, m);
    __shared__ float ws[32];
    if ((h & 31) == 0) ws[h >> 5] = ss;
    __syncthreads();
    float tot = ws[head * 2] + ws[head * 2 + 1];
    float inv = 1.0f / fmaxf(sqrtf(tot), 1e-12f);
    float kkn = kkx * inv;
    g_an[idx] = -kkn;
    g_bv[idx] = kkn * av;
    g_k[idx] = kv * (1.0f + (av - 1.0f) * kaw[h]);
}

// ----------------------------- sequential scan ------------------------------
__global__ void __launch_bounds__(256) scan_kernel()
{
    __shared__ float sh[2][6][64];
    int pair = blockIdx.x >> 1;
    int rsplit = blockIdx.x & 1;
    int tid = threadIdx.x;
    int vloc = tid >> 3;
    int q = tid & 7;
    int vrow = rsplit * 32 + vloc;
    int b = pair >> 4, h = pair & 15;
    int base0 = b * TT * HH + h * HDD;

    const float* lp = nullptr;
    float* sd0 = nullptr; float* sd1 = nullptr;
    if (tid < 96) {
        int aid = tid >> 4, wq = tid & 15;
        switch (aid) {
            case 0: lp = g_r;  break;
            case 1: lp = g_ew; break;
            case 2: lp = g_k;  break;
            case 3: lp = g_v;  break;
            case 4: lp = g_an; break;
            default: lp = g_bv; break;
        }
        lp += base0 + (wq << 2);
        sd0 = &sh[0][aid][wq << 2];
        sd1 = &sh[1][aid][wq << 2];
    }

    float S[8];
#pragma unroll
    for (int j = 0; j < 8; j++) S[j] = 0.f;

    if (tid < 96) *(float4*)sd0 = *(const float4*)lp;
    __syncthreads();

    for (int t = 0; t < TT; t++) {
        int cur = t & 1;
        if (tid < 96 && t + 1 < TT) {
            float4 tmp = *(const float4*)(lp + (size_t)(t + 1) * HH);
            *(float4*)(cur ? sd0 : sd1) = tmp;
        }
        const float (*cs)[64] = sh[cur];
        int c0 = q << 3;

        float4 aA = *(const float4*)&cs[4][c0];
        float4 aB = *(const float4*)&cs[4][c0 + 4];
        float sa = S[0]*aA.x + S[1]*aA.y + S[2]*aA.z + S[3]*aA.w
                 + S[4]*aB.x + S[5]*aB.y + S[6]*aB.z + S[7]*aB.w;
        sa += __shfl_xor_sync(~0u, sa, 1);
        sa += __shfl_xor_sync(~0u, sa, 2);
        sa += __shfl_xor_sync(~0u, sa, 4);

        float vv = cs[3][vrow];
        float4 eA = *(const float4*)&cs[1][c0];
        float4 eB = *(const float4*)&cs[1][c0 + 4];
        float4 kA = *(const float4*)&cs[2][c0];
        float4 kB = *(const float4*)&cs[2][c0 + 4];
        float4 bA = *(const float4*)&cs[5][c0];
        float4 bB = *(const float4*)&cs[5][c0 + 4];

        S[0] = fmaf(S[0], eA.x, fmaf(sa, bA.x, vv * kA.x));
        S[1] = fmaf(S[1], eA.y, fmaf(sa, bA.y, vv * kA.y));
        S[2] = fmaf(S[2], eA.z, fmaf(sa, bA.z, vv * kA.z));
        S[3] = fmaf(S[3], eA.w, fmaf(sa, bA.w, vv * kA.w));
        S[4] = fmaf(S[4], eB.x, fmaf(sa, bB.x, vv * kB.x));
        S[5] = fmaf(S[5], eB.y, fmaf(sa, bB.y, vv * kB.y));
        S[6] = fmaf(S[6], eB.z, fmaf(sa, bB.z, vv * kB.z));
        S[7] = fmaf(S[7], eB.w, fmaf(sa, bB.w, vv * kB.w));

        float4 rA = *(const float4*)&cs[0][c0];
        float4 rB = *(const float4*)&cs[0][c0 + 4];
        float oo = S[0]*rA.x + S[1]*rA.y + S[2]*rA.z + S[3]*rA.w
                 + S[4]*rB.x + S[5]*rB.y + S[6]*rB.z + S[7]*rB.w;
        oo += __shfl_xor_sync(~0u, oo, 1);
        oo += __shfl_xor_sync(~0u, oo, 2);
        oo += __shfl_xor_sync(~0u, oo, 4);
        if (q == 0) g_o[base0 + t * HH + vrow] = oo;
        __syncthreads();
    }
}

// ---------------- groupnorm + bonus-corr + gate -> y (bf16 hi/lo) ----------
__global__ void finalmix_kernel(const float* __restrict__ rkw,
                                const float* __restrict__ gnw,
                                const float* __restrict__ gnb)
{
    int bt = blockIdx.x;
    int head = threadIdx.x >> 5;
    int ld = threadIdx.x & 31;
    int base = bt * HH + head * HDD;
    int i0 = base + ld, i1 = base + 32 + ld;
    float o0 = g_o[i0], o1 = g_o[i1];
    float r0 = g_r[i0], r1 = g_r[i1];
    float k0 = g_k[i0], k1 = g_k[i1];
    float v0 = g_v[i0], v1 = g_v[i1];
    int h0 = head * HDD + ld, h1 = h0 + 32;

    float s  = o0 + o1;
    float qq = o0 * o0 + o1 * o1;
    float rk = r0 * k0 * rkw[h0] + r1 * k1 * rkw[h1];
#pragma unroll
    for (int m = 16; m >= 1; m >>= 1) {
        s  += __shfl_xor_sync(~0u, s,  m);
        qq += __shfl_xor_sync(~0u, qq, m);
        rk += __shfl_xor_sync(~0u, rk, m);
    }
    float mu = s * (1.0f / 64.0f);
    float var = qq * (1.0f / 64.0f) - mu * mu;
    float is = rsqrtf(var + GN_EPS);
    float y0 = (fmaf((o0 - mu) * is, gnw[h0], gnb[h0]) + rk * v0) * g_g[i0];
    float y1 = (fmaf((o1 - mu) * is, gnw[h1], gnb[h1]) + rk * v1) * g_g[i1];
    __nv_bfloat16 yh0 = __float2bfloat16(y0);
    __nv_bfloat16 yh1 = __float2bfloat16(y1);
    g_yH[i0] = yh0; g_yL[i0] = __float2bfloat16(y0 - __bfloat162float(yh0));
    g_yH[i1] = yh1; g_yL[i1] = __float2bfloat16(y1 - __bfloat162float(yh1));
}

// ----------------------------- host ----------------------------------------
extern "C" void kernel_launch(void* const* d_in, const int* in_sizes, int n_in,
                              void* d_out, int out_size)
{
    const float* hs  = (const float*)d_in[0];
    const float* vfi = (const float*)d_in[1];
    const float* x_r = (const float*)d_in[2];
    const float* x_w = (const float*)d_in[3];
    const float* x_k = (const float*)d_in[4];
    const float* x_v = (const float*)d_in[5];
    const float* x_a = (const float*)d_in[6];
    const float* x_g = (const float*)d_in[7];
    const float* k_k = (const float*)d_in[8];
    const float* k_a = (const float*)d_in[9];
    const float* r_k = (const float*)d_in[10];
    const float* W_r = (const float*)d_in[11];
    const float* W_k = (const float*)d_in[12];
    const float* W_v = (const float*)d_in[13];
    const float* W_o = (const float*)d_in[14];
    const float* wA  = (const float*)d_in[15];
    const float* wB  = (const float*)d_in[16];
    const float* wb  = (const float*)d_in[17];
    const float* vA  = (const float*)d_in[18];
    const float* vB  = (const float*)d_in[19];
    const float* vb  = (const float*)d_in[20];
    const float* aA  = (const float*)d_in[21];
    const float* aB  = (const float*)d_in[22];
    const float* ab  = (const float*)d_in[23];
    const float* gA  = (const float*)d_in[24];
    const float* gB  = (const float*)d_in[25];
    const float* gnw = (const float*)d_in[26];
    const float* gnb = (const float*)d_in[27];

    float *rb, *ewb, *kb, *v0b, *vb2, *ab2, *gb2;
    cudaGetSymbolAddress((void**)&rb,  g_r);
    cudaGetSymbolAddress((void**)&ewb, g_ew);
    cudaGetSymbolAddress((void**)&kb,  g_k);
    cudaGetSymbolAddress((void**)&v0b, g_v0);
    cudaGetSymbolAddress((void**)&vb2, g_v);
    cudaGetSymbolAddress((void**)&ab2, g_a);
    cudaGetSymbolAddress((void**)&gb2, g_g);

    __nv_bfloat16 *WrH, *WrL, *WkH, *WkL, *WvH, *WvL, *WoH, *WoL;
    __nv_bfloat16 *wBH, *wBL, *vBH, *vBL, *aBH, *aBL, *gBH, *gBL;
    __nv_bfloat16 *xrH, *xrL, *xkH, *xkL, *xvH, *xvL;
    __nv_bfloat16 *t1H, *t1L, *t2H, *t2L, *t3H, *t3L, *t4H, *t4L, *yH, *yL;
    cudaGetSymbolAddress((void**)&WrH, g_WrH); cudaGetSymbolAddress((void**)&WrL, g_WrL);
    cudaGetSymbolAddress((void**)&WkH, g_WkH); cudaGetSymbolAddress((void**)&WkL, g_WkL);
    cudaGetSymbolAddress((void**)&WvH, g_WvH); cudaGetSymbolAddress((void**)&WvL, g_WvL);
    cudaGetSymbolAddress((void**)&WoH, g_WoH); cudaGetSymbolAddress((void**)&WoL, g_WoL);
    cudaGetSymbolAddress((void**)&wBH, g_wBH); cudaGetSymbolAddress((void**)&wBL, g_wBL);
    cudaGetSymbolAddress((void**)&vBH, g_vBH); cudaGetSymbolAddress((void**)&vBL, g_vBL);
    cudaGetSymbolAddress((void**)&aBH, g_aBH); cudaGetSymbolAddress((void**)&aBL, g_aBL);
    cudaGetSymbolAddress((void**)&gBH, g_gBH); cudaGetSymbolAddress((void**)&gBL, g_gBL);
    cudaGetSymbolAddress((void**)&xrH, g_xrH); cudaGetSymbolAddress((void**)&xrL, g_xrL);
    cudaGetSymbolAddress((void**)&xkH, g_xkH); cudaGetSymbolAddress((void**)&xkL, g_xkL);
    cudaGetSymbolAddress((void**)&xvH, g_xvH); cudaGetSymbolAddress((void**)&xvL, g_xvL);
    cudaGetSymbolAddress((void**)&t1H, g_t1H); cudaGetSymbolAddress((void**)&t1L, g_t1L);
    cudaGetSymbolAddress((void**)&t2H, g_t2H); cudaGetSymbolAddress((void**)&t2L, g_t2L);
    cudaGetSymbolAddress((void**)&t3H, g_t3H); cudaGetSymbolAddress((void**)&t3L, g_t3L);
    cudaGetSymbolAddress((void**)&t4H, g_t4H); cudaGetSymbolAddress((void**)&t4L, g_t4L);
    cudaGetSymbolAddress((void**)&yH,  g_yH);  cudaGetSymbolAddress((void**)&yL,  g_yL);

    cudaFuncSetAttribute(tgemm_kernel<0>, cudaFuncAttributeMaxDynamicSharedMemorySize, TG_SMEM);
    cudaFuncSetAttribute(tgemm_kernel<3>, cudaFuncAttributeMaxDynamicSharedMemorySize, TG_SMEM);
    cudaFuncSetAttribute(tgemm_kernel<4>, cudaFuncAttributeMaxDynamicSharedMemorySize, TG_SMEM);
    cudaFuncSetAttribute(tgemm_kernel<5>, cudaFuncAttributeMaxDynamicSharedMemorySize, TG_SMEM);
    cudaFuncSetAttribute(dgemm_kernel,    cudaFuncAttributeMaxDynamicSharedMemorySize, DG_SMEM);

    dim3 blk(256);
    dim3 gT(HH / 128, BT / 128);
    dim3 gD(6, BT / 128);
    dim3 cblk(32, 8);

    // 0: all weight transposes + bf16 splits
    convw_all_kernel<<<4800, cblk>>>(W_r, W_k, W_v, W_o, wB, vB, aB, gB, wA, vA, aA, gA);

    // 1: token-shift mixes -> bf16 hi/lo
    prep_kernel<<<BTH / 4 / 256, 256>>>(hs, x_r, x_w, x_k, x_v, x_a, x_g);

    // 2-4: big projections
    tgemm_kernel<0><<<gT, blk, TG_SMEM>>>(xrH, xrL, WrH, WrL, rb,  BT, HH, HH, nullptr, nullptr, nullptr);
    tgemm_kernel<0><<<gT, blk, TG_SMEM>>>(xkH, xkL, WkH, WkL, kb,  BT, HH, HH, nullptr, nullptr, nullptr);
    tgemm_kernel<0><<<gT, blk, TG_SMEM>>>(xvH, xvL, WvH, WvL, v0b, BT, HH, HH, nullptr, nullptr, nullptr);

    // 5: batched LoRA/gate down-projections
    dgemm_kernel<<<gD, blk, DG_SMEM>>>();

    // 6-9: up-projections with fused epilogues
    tgemm_kernel<4><<<gT, blk, TG_SMEM>>>(t1H, t1L, wBH, wBL, ewb, BT, HH, 64, wb, nullptr, nullptr);
    tgemm_kernel<5><<<gT, blk, TG_SMEM>>>(t2H, t2L, vBH, vBL, vb2, BT, HH, 64, vb, v0b, vfi);
    tgemm_kernel<3><<<gT, blk, TG_SMEM>>>(t3H, t3L, aBH, aBL, ab2, BT, HH, 64, ab, nullptr, nullptr);
    tgemm_kernel<0><<<gT, blk, TG_SMEM>>>(t4H, t4L, gBH, gBL, gb2, BT, HH, 160, nullptr, nullptr, nullptr);

    // 10: kk normalize / k scale / scan coefficient vectors
    postproj_kernel<<<BT, 1024>>>(k_k, k_a);

    // 11: sequential RWKV7 scan
    scan_kernel<<<128, 256>>>();

    // 12: groupnorm + correction + gate -> y (bf16 hi/lo)
    finalmix_kernel<<<BT, 512>>>(r_k, gnw, gnb);

    // 13: output projection
    tgemm_kernel<0><<<gT, blk, TG_SMEM>>>(yH, yL, WoH, WoL, (float*)d_out, BT, HH, HH,
                                          nullptr, nullptr, nullptr);
}

// round 15
// speedup vs baseline: 1.7481x; 1.4829x over previous
#include <cuda_runtime.h>
#include <cuda_bf16.h>
#include <stdint.h>
#include <math.h>

// ---------------------------------------------------------------------------
// RWKV7 attention block, B=4 T=2048 H=1024 NH=16 HD=64.
// All GEMMs: mma.sync bf16 hi/lo split, fp32 accum, cp.async staging.
// Scan: cp.async ring buffer (depth 8, prefetch distance 6) to hide
// global-load latency that previously sat on every step's critical path.
// ---------------------------------------------------------------------------

#define BB   4
#define TT   2048
#define HH   1024
#define HDD  64
#define NHH  16
#define BT   (BB*TT)        // 8192 tokens
#define BTH  (BT*HH)        // 8388608
#define DECAY_LOG_SCALE (-0.6065306597126334f)
#define GN_EPS (64.0f*1e-5f)

// ----------------------------- scratch ------------------------------------
static __device__ float g_r[BTH], g_ew[BTH], g_k[BTH], g_v0[BTH], g_v[BTH], g_a[BTH];
static __device__ float g_an[BTH], g_bv[BTH], g_g[BTH], g_o[BTH];
static __device__ __nv_bfloat16 g_xrH[BTH], g_xrL[BTH], g_xwH[BTH], g_xwL[BTH];
static __device__ __nv_bfloat16 g_xkH[BTH], g_xkL[BTH], g_xvH[BTH], g_xvL[BTH];
static __device__ __nv_bfloat16 g_xaH[BTH], g_xaL[BTH], g_xgH[BTH], g_xgL[BTH];
static __device__ __nv_bfloat16 g_t1H[BT*64], g_t1L[BT*64], g_t2H[BT*64], g_t2L[BT*64];
static __device__ __nv_bfloat16 g_t3H[BT*64], g_t3L[BT*64], g_t4H[BT*160], g_t4L[BT*160];
static __device__ __nv_bfloat16 g_yH[BTH], g_yL[BTH];

static __device__ __nv_bfloat16 g_WrH[HH*HH], g_WrL[HH*HH];
static __device__ __nv_bfloat16 g_WkH[HH*HH], g_WkL[HH*HH];
static __device__ __nv_bfloat16 g_WvH[HH*HH], g_WvL[HH*HH];
static __device__ __nv_bfloat16 g_WoH[HH*HH], g_WoL[HH*HH];
static __device__ __nv_bfloat16 g_wBH[HH*64], g_wBL[HH*64];
static __device__ __nv_bfloat16 g_vBH[HH*64], g_vBL[HH*64];
static __device__ __nv_bfloat16 g_aBH[HH*64], g_aBL[HH*64];
static __device__ __nv_bfloat16 g_gBH[HH*160], g_gBL[HH*160];
static __device__ __nv_bfloat16 g_wAH[64*HH], g_wAL[64*HH];
static __device__ __nv_bfloat16 g_vAH[64*HH], g_vAL[64*HH];
static __device__ __nv_bfloat16 g_aAH[64*HH], g_aAL[64*HH];
static __device__ __nv_bfloat16 g_gAH[160*HH], g_gAL[160*HH];

__device__ __forceinline__ float sigf(float x) { return 1.0f / (1.0f + expf(-x)); }

__device__ __forceinline__ uint32_t pack_bf2(__nv_bfloat16 lo, __nv_bfloat16 hi) {
    return (uint32_t)__bfloat16_as_ushort(lo) | ((uint32_t)__bfloat16_as_ushort(hi) << 16);
}

__device__ __forceinline__ uint32_t smem_u32(const void* p) {
    uint32_t a;
    asm("{ .reg .u64 t; cvta.to.shared.u64 t, %1; cvt.u32.u64 %0, t; }" : "=r"(a) : "l"(p));
    return a;
}

__device__ __forceinline__ void cpa16(uint32_t dst, const void* src) {
    asm volatile("cp.async.ca.shared.global [%0], [%1], 16;" :: "r"(dst), "l"(src));
}
#define CP_COMMIT() asm volatile("cp.async.commit_group;" ::: "memory")
#define CP_WAIT0()  asm volatile("cp.async.wait_group 0;" ::: "memory")

__device__ __forceinline__ void ldsm4(uint32_t& r0, uint32_t& r1, uint32_t& r2, uint32_t& r3,
                                      uint32_t addr)
{
    asm volatile("ldmatrix.sync.aligned.m8n8.x4.shared.b16 {%0,%1,%2,%3}, [%4];"
                 : "=r"(r0), "=r"(r1), "=r"(r2), "=r"(r3) : "r"(addr));
}

__device__ __forceinline__ void mma16816(float* c,
                                         uint32_t a0, uint32_t a1, uint32_t a2, uint32_t a3,
                                         uint32_t b0, uint32_t b1)
{
    asm volatile("mma.sync.aligned.m16n8k16.row.col.f32.bf16.bf16.f32 "
                 "{%0,%1,%2,%3}, {%4,%5,%6,%7}, {%8,%9}, {%0,%1,%2,%3};"
                 : "+f"(c[0]), "+f"(c[1]), "+f"(c[2]), "+f"(c[3])
                 : "r"(a0), "r"(a1), "r"(a2), "r"(a3), "r"(b0), "r"(b1));
}

// ----------------------------- prep: token shift -> bf16 hi/lo -------------
__global__ void prep_kernel(const float* __restrict__ hs,
                            const float* __restrict__ mr, const float* __restrict__ mw,
                            const float* __restrict__ mk, const float* __restrict__ mv,
                            const float* __restrict__ ma, const float* __restrict__ mg)
{
    int i4 = blockIdx.x * blockDim.x + threadIdx.x;
    if (i4 >= BTH / 4) return;
    int i = i4 * 4;
    int t = (i / HH) % TT;
    int h = i % HH;
    float4 x = *(const float4*)(hs + i);
    float4 p = make_float4(0.f, 0.f, 0.f, 0.f);
    if (t > 0) p = *(const float4*)(hs + i - HH);
    float4 d = make_float4(p.x - x.x, p.y - x.y, p.z - x.z, p.w - x.w);
#define DOMIX(dH, dL, mp) { \
    float4 m4 = *(const float4*)((mp) + h); float4 o4; \
    o4.x = fmaf(d.x, m4.x, x.x); o4.y = fmaf(d.y, m4.y, x.y); \
    o4.z = fmaf(d.z, m4.z, x.z); o4.w = fmaf(d.w, m4.w, x.w); \
    __nv_bfloat16 h0 = __float2bfloat16(o4.x), h1 = __float2bfloat16(o4.y); \
    __nv_bfloat16 h2 = __float2bfloat16(o4.z), h3 = __float2bfloat16(o4.w); \
    __nv_bfloat16 l0 = __float2bfloat16(o4.x - __bfloat162float(h0)); \
    __nv_bfloat16 l1 = __float2bfloat16(o4.y - __bfloat162float(h1)); \
    __nv_bfloat16 l2 = __float2bfloat16(o4.z - __bfloat162float(h2)); \
    __nv_bfloat16 l3 = __float2bfloat16(o4.w - __bfloat162float(h3)); \
    uint2 hv; hv.x = pack_bf2(h0, h1); hv.y = pack_bf2(h2, h3); \
    uint2 lv; lv.x = pack_bf2(l0, l1); lv.y = pack_bf2(l2, l3); \
    *(uint2*)((dH) + i) = hv; *(uint2*)((dL) + i) = lv; }
    DOMIX(g_xrH, g_xrL, mr) DOMIX(g_xwH, g_xwL, mw) DOMIX(g_xkH, g_xkL, mk)
    DOMIX(g_xvH, g_xvL, mv) DOMIX(g_xaH, g_xaL, ma) DOMIX(g_xgH, g_xgL, mg)
#undef DOMIX
}

// ----------------- weight transpose + bf16 hi/lo split (all-in-one) -------
__global__ void convw_all_kernel(const float* __restrict__ Wr, const float* __restrict__ Wk,
                                 const float* __restrict__ Wv, const float* __restrict__ Wo,
                                 const float* __restrict__ wB, const float* __restrict__ vB,
                                 const float* __restrict__ aB, const float* __restrict__ gB,
                                 const float* __restrict__ wA, const float* __restrict__ vA,
                                 const float* __restrict__ aA, const float* __restrict__ gA)
{
    __shared__ float ts[32][33];
    int bidx = blockIdx.x;
    const float* W; __nv_bfloat16 *Bh, *Bl;
    int SK, SN, nb, kb;
    if (bidx < 4096) {
        int m = bidx >> 10, local = bidx & 1023;
        SK = HH; SN = HH;
        nb = (local & 31) * 32; kb = (local >> 5) * 32;
        switch (m) {
            case 0: W = Wr; Bh = g_WrH; Bl = g_WrL; break;
            case 1: W = Wk; Bh = g_WkH; Bl = g_WkL; break;
            case 2: W = Wv; Bh = g_WvH; Bl = g_WvL; break;
            default: W = Wo; Bh = g_WoH; Bl = g_WoL; break;
        }
    } else if (bidx < 4288) {
        int m = (bidx - 4096) >> 6, local = (bidx - 4096) & 63;
        SK = 64; SN = HH;
        nb = (local & 31) * 32; kb = (local >> 5) * 32;
        switch (m) {
            case 0: W = wB; Bh = g_wBH; Bl = g_wBL; break;
            case 1: W = vB; Bh = g_vBH; Bl = g_vBL; break;
            default: W = aB; Bh = g_aBH; Bl = g_aBL; break;
        }
    } else if (bidx < 4448) {
        int local = bidx - 4288;
        SK = 160; SN = HH;
        nb = (local & 31) * 32; kb = (local >> 5) * 32;
        W = gB; Bh = g_gBH; Bl = g_gBL;
    } else if (bidx < 4640) {
        int m = (bidx - 4448) >> 6, local = (bidx - 4448) & 63;
        SK = HH; SN = 64;
        nb = (local & 1) * 32; kb = (local >> 1) * 32;
        switch (m) {
            case 0: W = wA; Bh = g_wAH; Bl = g_wAL; break;
            case 1: W = vA; Bh = g_vAH; Bl = g_vAL; break;
            default: W = aA; Bh = g_aAH; Bl = g_aAL; break;
        }
    } else {
        int local = bidx - 4640;
        SK = HH; SN = 160;
        nb = (local % 5) * 32; kb = (local / 5) * 32;
        W = gA; Bh = g_gAH; Bl = g_gAL;
    }
    int tx = threadIdx.x, ty = threadIdx.y;  // 32 x 8
    for (int i = ty; i < 32; i += 8)
        ts[i][tx] = W[(size_t)(kb + i) * SN + nb + tx];
    __syncthreads();
    for (int i = ty; i < 32; i += 8) {
        float x = ts[tx][i];
        __nv_bfloat16 h = __float2bfloat16(x);
        __nv_bfloat16 l = __float2bfloat16(x - __bfloat162float(h));
        size_t o = (size_t)(nb + i) * SK + kb + tx;
        Bh[o] = h; Bl[o] = l;
    }
}

// --------------------- mma.sync GEMM: C = A @ Bt^T -------------------------
#define LDS 40                       // padded row length (bf16 elems)
#define ABUF (128*LDS)
#define TG_SMEM (8*ABUF*2)           // 81920 B

template <int EPI>
__global__ void __launch_bounds__(256, 2)
tgemm_kernel(const __nv_bfloat16* __restrict__ Ah, const __nv_bfloat16* __restrict__ Al,
             const __nv_bfloat16* __restrict__ Bh, const __nv_bfloat16* __restrict__ Bl,
             float* __restrict__ C, int M, int N, int K,
             const float* __restrict__ bias,
             const float* __restrict__ e0, const float* __restrict__ e1)
{
    extern __shared__ char smem[];
    const uint32_t sA = smem_u32(smem);
    const uint32_t sB = sA + 4 * ABUF * 2;
    const int tid = threadIdx.x;
    const int wid = tid >> 5, lane = tid & 31;
    const int wm = wid >> 2, wn = wid & 3;
    const int m0 = blockIdx.y * 128, n0 = blockIdx.x * 128;

    float acc[4][4][4];
#pragma unroll
    for (int i = 0; i < 4; i++)
#pragma unroll
        for (int j = 0; j < 4; j++)
#pragma unroll
            for (int f = 0; f < 4; f++) acc[i][j][f] = 0.f;

    const int nC = K >> 5;

#define T_LOAD(kc, b) { \
        int k0 = (kc) << 5; \
        uint32_t aH = sA + (b) * (4 * ABUF); \
        uint32_t bH = sB + (b) * (4 * ABUF); \
        _Pragma("unroll") \
        for (int i = 0; i < 2; i++) { \
            int idx = tid + i * 256; \
            int r = idx >> 2, c = (idx & 3) << 3; \
            uint32_t so = (uint32_t)(r * LDS + c) * 2; \
            size_t ga = (size_t)(m0 + r) * K + k0 + c; \
            size_t gb = (size_t)(n0 + r) * K + k0 + c; \
            cpa16(aH + so, Ah + ga); \
            cpa16(aH + 2 * ABUF + so, Al + ga); \
            cpa16(bH + so, Bh + gb); \
            cpa16(bH + 2 * ABUF + so, Bl + gb); \
        } }

    T_LOAD(0, 0)
    CP_COMMIT();
    CP_WAIT0();
    __syncthreads();

    for (int ic = 0; ic < nC; ic++) {
        int buf = ic & 1;
        if (ic + 1 < nC) { T_LOAD(ic + 1, buf ^ 1) CP_COMMIT(); }

        {
            uint32_t aBaseH = sA + buf * (4 * ABUF);
            uint32_t aBaseL = aBaseH + 2 * ABUF;
            uint32_t bBaseH = sB + buf * (4 * ABUF);
            uint32_t bBaseL = bBaseH + 2 * ABUF;
#pragma unroll
            for (int kk = 0; kk < 32; kk += 16) {
                uint32_t ah[4][4], al[4][4], bh[2][4], bl[2][4];
#pragma unroll
                for (int i = 0; i < 4; i++) {
                    int row = wm * 64 + i * 16 + (lane & 15);
                    int col = kk + ((lane >> 4) << 3);
                    uint32_t off = (uint32_t)(row * LDS + col) * 2;
                    ldsm4(ah[i][0], ah[i][1], ah[i][2], ah[i][3], aBaseH + off);
                    ldsm4(al[i][0], al[i][1], al[i][2], al[i][3], aBaseL + off);
                }
#pragma unroll
                for (int jp = 0; jp < 2; jp++) {
                    int row = wn * 32 + jp * 16 + ((lane >> 4) << 3) + (lane & 7);
                    int col = kk + ((lane >> 3) & 1) * 8;
                    uint32_t off = (uint32_t)(row * LDS + col) * 2;
                    ldsm4(bh[jp][0], bh[jp][1], bh[jp][2], bh[jp][3], bBaseH + off);
                    ldsm4(bl[jp][0], bl[jp][1], bl[jp][2], bl[jp][3], bBaseL + off);
                }
#pragma unroll
                for (int i = 0; i < 4; i++)
#pragma unroll
                    for (int j = 0; j < 4; j++) {
                        uint32_t b0h = bh[j >> 1][(j & 1) * 2], b1h = bh[j >> 1][(j & 1) * 2 + 1];
                        uint32_t b0l = bl[j >> 1][(j & 1) * 2], b1l = bl[j >> 1][(j & 1) * 2 + 1];
                        mma16816(acc[i][j], ah[i][0], ah[i][1], ah[i][2], ah[i][3], b0h, b1h);
                        mma16816(acc[i][j], ah[i][0], ah[i][1], ah[i][2], ah[i][3], b0l, b1l);
                        mma16816(acc[i][j], al[i][0], al[i][1], al[i][2], al[i][3], b0h, b1h);
                    }
            }
        }

        if (ic + 1 < nC) {
            CP_WAIT0();
            __syncthreads();
        }
    }

    // ---- epilogue ----
    int g = lane >> 2, tig = lane & 3;
#pragma unroll
    for (int i = 0; i < 4; i++) {
        int r0 = m0 + wm * 64 + i * 16 + g;
#pragma unroll
        for (int j = 0; j < 4; j++) {
            int col = n0 + wn * 32 + j * 8 + tig * 2;
            float2 v0 = make_float2(acc[i][j][0], acc[i][j][1]);
            float2 v1 = make_float2(acc[i][j][2], acc[i][j][3]);
            if (EPI == 3 || EPI == 4 || EPI == 5) {
                float b0 = bias[col], b1 = bias[col + 1];
                v0.x = sigf(v0.x + b0); v0.y = sigf(v0.y + b1);
                v1.x = sigf(v1.x + b0); v1.y = sigf(v1.y + b1);
                if (EPI == 4) {
                    v0.x = expf(DECAY_LOG_SCALE * v0.x); v0.y = expf(DECAY_LOG_SCALE * v0.y);
                    v1.x = expf(DECAY_LOG_SCALE * v1.x); v1.y = expf(DECAY_LOG_SCALE * v1.y);
                } else if (EPI == 5) {
                    size_t o0 = (size_t)r0 * N + col, o1 = (size_t)(r0 + 8) * N + col;
                    float2 a0 = *(const float2*)(e0 + o0);
                    float2 c0v = *(const float2*)(e1 + o0);
                    float2 a1 = *(const float2*)(e0 + o1);
                    float2 c1v = *(const float2*)(e1 + o1);
                    v0.x = fmaf(v0.x, c0v.x - a0.x, a0.x);
                    v0.y = fmaf(v0.y, c0v.y - a0.y, a0.y);
                    v1.x = fmaf(v1.x, c1v.x - a1.x, a1.x);
                    v1.y = fmaf(v1.y, c1v.y - a1.y, a1.y);
                }
            }
            *(float2*)(C + (size_t)r0 * N + col) = v0;
            *(float2*)(C + (size_t)(r0 + 8) * N + col) = v1;
        }
    }
}

// ------------- batched down-projection GEMM (mma, 128x64 tiles) ------------
#define DBBUF (64*LDS)
#define DG_SMEM ((4*ABUF + 4*DBBUF)*2)   // 61440 B

__global__ void __launch_bounds__(256, 2)
dgemm_kernel()
{
    extern __shared__ char smem[];
    const uint32_t sA = smem_u32(smem);
    const uint32_t sB = sA + 4 * ABUF * 2;
    const int tid = threadIdx.x;
    const int wid = tid >> 5, lane = tid & 31;
    const int wm = wid & 3, wn = (wid >> 2) & 1;
    const int m0 = blockIdx.y * 128;
    const int tix = blockIdx.x;

    const __nv_bfloat16 *Ah, *Al, *BH, *BL;
    __nv_bfloat16 *CH, *CL;
    int Nseg, n0, epi;
    if (tix == 0)      { Ah = g_xwH; Al = g_xwL; BH = g_wAH; BL = g_wAL; CH = g_t1H; CL = g_t1L; Nseg = 64;  n0 = 0; epi = 1; }
    else if (tix == 1) { Ah = g_xvH; Al = g_xvL; BH = g_vAH; BL = g_vAL; CH = g_t2H; CL = g_t2L; Nseg = 64;  n0 = 0; epi = 0; }
    else if (tix == 2) { Ah = g_xaH; Al = g_xaL; BH = g_aAH; BL = g_aAL; CH = g_t3H; CL = g_t3L; Nseg = 64;  n0 = 0; epi = 0; }
    else               { Ah = g_xgH; Al = g_xgL; BH = g_gAH; BL = g_gAL; CH = g_t4H; CL = g_t4L; Nseg = 160; n0 = (tix - 3) * 64; epi = 2; }

    const int K = HH;
    float acc[2][4][4];
#pragma unroll
    for (int i = 0; i < 2; i++)
#pragma unroll
        for (int j = 0; j < 4; j++)
#pragma unroll
            for (int f = 0; f < 4; f++) acc[i][j][f] = 0.f;

    const int nC = K >> 5;
    const int brow = tid >> 2, bc = (tid & 3) << 3;
    const bool bvalid = (n0 + brow) < Nseg;

    if (!bvalid) {
#pragma unroll
        for (int b = 0; b < 2; b++) {
            uint32_t bH = sB + b * (4 * DBBUF);
            uint32_t so = (uint32_t)(brow * LDS + bc) * 2;
            *(uint4*)(smem + (bH - sA) + so) = make_uint4(0, 0, 0, 0);
            *(uint4*)(smem + (bH + 2 * DBBUF - sA) + so) = make_uint4(0, 0, 0, 0);
        }
    }
    __syncthreads();

#define D_LOAD(kc, b) { \
        int k0 = (kc) << 5; \
        uint32_t aH = sA + (b) * (4 * ABUF); \
        uint32_t bH = sB + (b) * (4 * DBBUF); \
        _Pragma("unroll") \
        for (int i = 0; i < 2; i++) { \
            int idx = tid + i * 256; \
            int r = idx >> 2, c = (idx & 3) << 3; \
            uint32_t so = (uint32_t)(r * LDS + c) * 2; \
            size_t ga = (size_t)(m0 + r) * K + k0 + c; \
            cpa16(aH + so, Ah + ga); \
            cpa16(aH + 2 * ABUF + so, Al + ga); \
        } \
        if (bvalid) { \
            uint32_t so = (uint32_t)(brow * LDS + bc) * 2; \
            size_t gb = (size_t)(n0 + brow) * K + k0 + bc; \
            cpa16(bH + so, BH + gb); \
            cpa16(bH + 2 * DBBUF + so, BL + gb); \
        } }

    D_LOAD(0, 0)
    CP_COMMIT();
    CP_WAIT0();
    __syncthreads();

    for (int ic = 0; ic < nC; ic++) {
        int buf = ic & 1;
        if (ic + 1 < nC) { D_LOAD(ic + 1, buf ^ 1) CP_COMMIT(); }

        {
            uint32_t aBaseH = sA + buf * (4 * ABUF);
            uint32_t aBaseL = aBaseH + 2 * ABUF;
            uint32_t bBaseH = sB + buf * (4 * DBBUF);
            uint32_t bBaseL = bBaseH + 2 * DBBUF;
#pragma unroll
            for (int kk = 0; kk < 32; kk += 16) {
                uint32_t ah[2][4], al[2][4], bh[2][4], bl[2][4];
#pragma unroll
                for (int i = 0; i < 2; i++) {
                    int row = wm * 32 + i * 16 + (lane & 15);
                    int col = kk + ((lane >> 4) << 3);
                    uint32_t off = (uint32_t)(row * LDS + col) * 2;
                    ldsm4(ah[i][0], ah[i][1], ah[i][2], ah[i][3], aBaseH + off);
                    ldsm4(al[i][0], al[i][1], al[i][2], al[i][3], aBaseL + off);
                }
#pragma unroll
                for (int jp = 0; jp < 2; jp++) {
                    int row = wn * 32 + jp * 16 + ((lane >> 4) << 3) + (lane & 7);
                    int col = kk + ((lane >> 3) & 1) * 8;
                    uint32_t off = (uint32_t)(row * LDS + col) * 2;
                    ldsm4(bh[jp][0], bh[jp][1], bh[jp][2], bh[jp][3], bBaseH + off);
                    ldsm4(bl[jp][0], bl[jp][1], bl[jp][2], bl[jp][3], bBaseL + off);
                }
#pragma unroll
                for (int i = 0; i < 2; i++)
#pragma unroll
                    for (int j = 0; j < 4; j++) {
                        uint32_t b0h = bh[j >> 1][(j & 1) * 2], b1h = bh[j >> 1][(j & 1) * 2 + 1];
                        uint32_t b0l = bl[j >> 1][(j & 1) * 2], b1l = bl[j >> 1][(j & 1) * 2 + 1];
                        mma16816(acc[i][j], ah[i][0], ah[i][1], ah[i][2], ah[i][3], b0h, b1h);
                        mma16816(acc[i][j], ah[i][0], ah[i][1], ah[i][2], ah[i][3], b0l, b1l);
                        mma16816(acc[i][j], al[i][0], al[i][1], al[i][2], al[i][3], b0h, b1h);
                    }
            }
        }

        if (ic + 1 < nC) {
            CP_WAIT0();
            __syncthreads();
        }
    }

    // ---- epilogue: activation + bf16 hi/lo store ----
    int g = lane >> 2, tig = lane & 3;
#pragma unroll
    for (int i = 0; i < 2; i++) {
        int r0 = m0 + wm * 32 + i * 16 + g;
#pragma unroll
        for (int j = 0; j < 4; j++) {
            int gcol = n0 + wn * 32 + j * 8 + tig * 2;
            if (gcol >= Nseg) continue;
            float2 v0 = make_float2(acc[i][j][0], acc[i][j][1]);
            float2 v1 = make_float2(acc[i][j][2], acc[i][j][3]);
            if (epi == 1) {
                v0.x = tanhf(v0.x); v0.y = tanhf(v0.y);
                v1.x = tanhf(v1.x); v1.y = tanhf(v1.y);
            } else if (epi == 2) {
                v0.x = sigf(v0.x); v0.y = sigf(v0.y);
                v1.x = sigf(v1.x); v1.y = sigf(v1.y);
            }
#define STORE_HL(val2, roff) { \
            __nv_bfloat16 h0 = __float2bfloat16((val2).x), h1 = __float2bfloat16((val2).y); \
            __nv_bfloat16 l0 = __float2bfloat16((val2).x - __bfloat162float(h0)); \
            __nv_bfloat16 l1 = __float2bfloat16((val2).y - __bfloat162float(h1)); \
            size_t oo = (size_t)(roff) * Nseg + gcol; \
            *(uint32_t*)(CH + oo) = pack_bf2(h0, h1); \
            *(uint32_t*)(CL + oo) = pack_bf2(l0, l1); }
            STORE_HL(v0, r0)
            STORE_HL(v1, r0 + 8)
#undef STORE_HL
        }
    }
}

// --------------------- postproj: kk-normalize, k scale, a/b vecs -----------
__global__ void postproj_kernel(const float* __restrict__ kkw,
                                const float* __restrict__ kaw)
{
    int bt = blockIdx.x;
    int h = threadIdx.x;
    int head = h >> 6;
    int idx = bt * HH + h;
    float kv = g_k[idx], av = g_a[idx];
    float kkx = kv * kkw[h];
    float ss = kkx * kkx;
#pragma unroll
    for (int m = 16; m >= 1; m >>= 1) ss += __shfl_xor_sync(~0u, ss, m);
    __shared__ float ws[32];
    if ((h & 31) == 0) ws[h >> 5] = ss;
    __syncthreads();
    float tot = ws[head * 2] + ws[head * 2 + 1];
    float inv = 1.0f / fmaxf(sqrtf(tot), 1e-12f);
    float kkn = kkx * inv;
    g_an[idx] = -kkn;
    g_bv[idx] = kkn * av;
    g_k[idx] = kv * (1.0f + (av - 1.0f) * kaw[h]);
}

// ------------------- sequential scan: cp.async ring buffer ------------------
// 8-slot smem ring, prefetch distance 6, one commit group per step.
// Per-step critical path = barrier + compute chain; global-load latency is
// hidden 6 steps deep by the async copy engine.
__global__ void __launch_bounds__(256) scan_kernel()
{
    __shared__ float sh[8][6][64];   // 12 KB ring
    int pair = blockIdx.x >> 1;
    int rsplit = blockIdx.x & 1;
    int tid = threadIdx.x;
    int vloc = tid >> 3;
    int q = tid & 7;
    int vrow = rsplit * 32 + vloc;
    int b = pair >> 4, h = pair & 15;
    int base0 = b * TT * HH + h * HDD;

    const float* lp = nullptr;
    int aid = 0, wq = 0;
    const bool ldr = tid < 96;
    if (ldr) {
        aid = tid >> 4; wq = tid & 15;
        switch (aid) {
            case 0: lp = g_r;  break;
            case 1: lp = g_ew; break;
            case 2: lp = g_k;  break;
            case 3: lp = g_v;  break;
            case 4: lp = g_an; break;
            default: lp = g_bv; break;
        }
        lp += base0 + (wq << 2);
    }
    const uint32_t sbase = smem_u32(&sh[0][0][0]);
    const uint32_t soff = (uint32_t)((aid * 64 + (wq << 2)) * 4);   // bytes within slot
    const uint32_t SLOT = 6 * 64 * 4;                               // 1536 B per slot

    float S[8];
#pragma unroll
    for (int j = 0; j < 8; j++) S[j] = 0.f;

    // prologue: prefetch steps 0..5 (one commit group per step)
#pragma unroll
    for (int s = 0; s < 6; s++) {
        if (ldr) cpa16(sbase + (uint32_t)s * SLOT + soff, lp + (size_t)s * HH);
        CP_COMMIT();
    }

    for (int t = 0; t < TT; t++) {
        // issue prefetch for step t+6 into ring slot (t+6)&7
        if (ldr && t + 6 < TT)
            cpa16(sbase + (uint32_t)((t + 6) & 7) * SLOT + soff, lp + (size_t)(t + 6) * HH);
        CP_COMMIT();
        asm volatile("cp.async.wait_group 6;" ::: "memory");
        __syncthreads();

        const float (*cs)[64] = sh[t & 7];
        int c0 = q << 3;

        float4 aA = *(const float4*)&cs[4][c0];
        float4 aB = *(const float4*)&cs[4][c0 + 4];
        float sa = S[0]*aA.x + S[1]*aA.y + S[2]*aA.z + S[3]*aA.w
                 + S[4]*aB.x + S[5]*aB.y + S[6]*aB.z + S[7]*aB.w;
        sa += __shfl_xor_sync(~0u, sa, 1);
        sa += __shfl_xor_sync(~0u, sa, 2);
        sa += __shfl_xor_sync(~0u, sa, 4);

        float vv = cs[3][vrow];
        float4 eA = *(const float4*)&cs[1][c0];
        float4 eB = *(const float4*)&cs[1][c0 + 4];
        float4 kA = *(const float4*)&cs[2][c0];
        float4 kB = *(const float4*)&cs[2][c0 + 4];
        float4 bA = *(const float4*)&cs[5][c0];
        float4 bB = *(const float4*)&cs[5][c0 + 4];

        S[0] = fmaf(S[0], eA.x, fmaf(sa, bA.x, vv * kA.x));
        S[1] = fmaf(S[1], eA.y, fmaf(sa, bA.y, vv * kA.y));
        S[2] = fmaf(S[2], eA.z, fmaf(sa, bA.z, vv * kA.z));
        S[3] = fmaf(S[3], eA.w, fmaf(sa, bA.w, vv * kA.w));
        S[4] = fmaf(S[4], eB.x, fmaf(sa, bB.x, vv * kB.x));
        S[5] = fmaf(S[5], eB.y, fmaf(sa, bB.y, vv * kB.y));
        S[6] = fmaf(S[6], eB.z, fmaf(sa, bB.z, vv * kB.z));
        S[7] = fmaf(S[7], eB.w, fmaf(sa, bB.w, vv * kB.w));

        float4 rA = *(const float4*)&cs[0][c0];
        float4 rB = *(const float4*)&cs[0][c0 + 4];
        float oo = S[0]*rA.x + S[1]*rA.y + S[2]*rA.z + S[3]*rA.w
                 + S[4]*rB.x + S[5]*rB.y + S[6]*rB.z + S[7]*rB.w;
        oo += __shfl_xor_sync(~0u, oo, 1);
        oo += __shfl_xor_sync(~0u, oo, 2);
        oo += __shfl_xor_sync(~0u, oo, 4);
        if (q == 0) g_o[base0 + t * HH + vrow] = oo;
    }
}

// ---------------- groupnorm + bonus-corr + gate -> y (bf16 hi/lo) ----------
__global__ void finalmix_kernel(const float* __restrict__ rkw,
                                const float* __restrict__ gnw,
                                const float* __restrict__ gnb)
{
    int bt = blockIdx.x;
    int head = threadIdx.x >> 5;
    int ld = threadIdx.x & 31;
    int base = bt * HH + head * HDD;
    int i0 = base + ld, i1 = base + 32 + ld;
    float o0 = g_o[i0], o1 = g_o[i1];
    float r0 = g_r[i0], r1 = g_r[i1];
    float k0 = g_k[i0], k1 = g_k[i1];
    float v0 = g_v[i0], v1 = g_v[i1];
    int h0 = head * HDD + ld, h1 = h0 + 32;

    float s  = o0 + o1;
    float qq = o0 * o0 + o1 * o1;
    float rk = r0 * k0 * rkw[h0] + r1 * k1 * rkw[h1];
#pragma unroll
    for (int m = 16; m >= 1; m >>= 1) {
        s  += __shfl_xor_sync(~0u, s,  m);
        qq += __shfl_xor_sync(~0u, qq, m);
        rk += __shfl_xor_sync(~0u, rk, m);
    }
    float mu = s * (1.0f / 64.0f);
    float var = qq * (1.0f / 64.0f) - mu * mu;
    float is = rsqrtf(var + GN_EPS);
    float y0 = (fmaf((o0 - mu) * is, gnw[h0], gnb[h0]) + rk * v0) * g_g[i0];
    float y1 = (fmaf((o1 - mu) * is, gnw[h1], gnb[h1]) + rk * v1) * g_g[i1];
    __nv_bfloat16 yh0 = __float2bfloat16(y0);
    __nv_bfloat16 yh1 = __float2bfloat16(y1);
    g_yH[i0] = yh0; g_yL[i0] = __float2bfloat16(y0 - __bfloat162float(yh0));
    g_yH[i1] = yh1; g_yL[i1] = __float2bfloat16(y1 - __bfloat162float(yh1));
}

// ----------------------------- host ----------------------------------------
extern "C" void kernel_launch(void* const* d_in, const int* in_sizes, int n_in,
                              void* d_out, int out_size)
{
    const float* hs  = (const float*)d_in[0];
    const float* vfi = (const float*)d_in[1];
    const float* x_r = (const float*)d_in[2];
    const float* x_w = (const float*)d_in[3];
    const float* x_k = (const float*)d_in[4];
    const float* x_v = (const float*)d_in[5];
    const float* x_a = (const float*)d_in[6];
    const float* x_g = (const float*)d_in[7];
    const float* k_k = (const float*)d_in[8];
    const float* k_a = (const float*)d_in[9];
    const float* r_k = (const float*)d_in[10];
    const float* W_r = (const float*)d_in[11];
    const float* W_k = (const float*)d_in[12];
    const float* W_v = (const float*)d_in[13];
    const float* W_o = (const float*)d_in[14];
    const float* wA  = (const float*)d_in[15];
    const float* wB  = (const float*)d_in[16];
    const float* wb  = (const float*)d_in[17];
    const float* vA  = (const float*)d_in[18];
    const float* vB  = (const float*)d_in[19];
    const float* vb  = (const float*)d_in[20];
    const float* aA  = (const float*)d_in[21];
    const float* aB  = (const float*)d_in[22];
    const float* ab  = (const float*)d_in[23];
    const float* gA  = (const float*)d_in[24];
    const float* gB  = (const float*)d_in[25];
    const float* gnw = (const float*)d_in[26];
    const float* gnb = (const float*)d_in[27];

    float *rb, *ewb, *kb, *v0b, *vb2, *ab2, *gb2;
    cudaGetSymbolAddress((void**)&rb,  g_r);
    cudaGetSymbolAddress((void**)&ewb, g_ew);
    cudaGetSymbolAddress((void**)&kb,  g_k);
    cudaGetSymbolAddress((void**)&v0b, g_v0);
    cudaGetSymbolAddress((void**)&vb2, g_v);
    cudaGetSymbolAddress((void**)&ab2, g_a);
    cudaGetSymbolAddress((void**)&gb2, g_g);

    __nv_bfloat16 *WrH, *WrL, *WkH, *WkL, *WvH, *WvL, *WoH, *WoL;
    __nv_bfloat16 *wBH, *wBL, *vBH, *vBL, *aBH, *aBL, *gBH, *gBL;
    __nv_bfloat16 *xrH, *xrL, *xkH, *xkL, *xvH, *xvL;
    __nv_bfloat16 *t1H, *t1L, *t2H, *t2L, *t3H, *t3L, *t4H, *t4L, *yH, *yL;
    cudaGetSymbolAddress((void**)&WrH, g_WrH); cudaGetSymbolAddress((void**)&WrL, g_WrL);
    cudaGetSymbolAddress((void**)&WkH, g_WkH); cudaGetSymbolAddress((void**)&WkL, g_WkL);
    cudaGetSymbolAddress((void**)&WvH, g_WvH); cudaGetSymbolAddress((void**)&WvL, g_WvL);
    cudaGetSymbolAddress((void**)&WoH, g_WoH); cudaGetSymbolAddress((void**)&WoL, g_WoL);
    cudaGetSymbolAddress((void**)&wBH, g_wBH); cudaGetSymbolAddress((void**)&wBL, g_wBL);
    cudaGetSymbolAddress((void**)&vBH, g_vBH); cudaGetSymbolAddress((void**)&vBL, g_vBL);
    cudaGetSymbolAddress((void**)&aBH, g_aBH); cudaGetSymbolAddress((void**)&aBL, g_aBL);
    cudaGetSymbolAddress((void**)&gBH, g_gBH); cudaGetSymbolAddress((void**)&gBL, g_gBL);
    cudaGetSymbolAddress((void**)&xrH, g_xrH); cudaGetSymbolAddress((void**)&xrL, g_xrL);
    cudaGetSymbolAddress((void**)&xkH, g_xkH); cudaGetSymbolAddress((void**)&xkL, g_xkL);
    cudaGetSymbolAddress((void**)&xvH, g_xvH); cudaGetSymbolAddress((void**)&xvL, g_xvL);
    cudaGetSymbolAddress((void**)&t1H, g_t1H); cudaGetSymbolAddress((void**)&t1L, g_t1L);
    cudaGetSymbolAddress((void**)&t2H, g_t2H); cudaGetSymbolAddress((void**)&t2L, g_t2L);
    cudaGetSymbolAddress((void**)&t3H, g_t3H); cudaGetSymbolAddress((void**)&t3L, g_t3L);
    cudaGetSymbolAddress((void**)&t4H, g_t4H); cudaGetSymbolAddress((void**)&t4L, g_t4L);
    cudaGetSymbolAddress((void**)&yH,  g_yH);  cudaGetSymbolAddress((void**)&yL,  g_yL);

    cudaFuncSetAttribute(tgemm_kernel<0>, cudaFuncAttributeMaxDynamicSharedMemorySize, TG_SMEM);
    cudaFuncSetAttribute(tgemm_kernel<3>, cudaFuncAttributeMaxDynamicSharedMemorySize, TG_SMEM);
    cudaFuncSetAttribute(tgemm_kernel<4>, cudaFuncAttributeMaxDynamicSharedMemorySize, TG_SMEM);
    cudaFuncSetAttribute(tgemm_kernel<5>, cudaFuncAttributeMaxDynamicSharedMemorySize, TG_SMEM);
    cudaFuncSetAttribute(dgemm_kernel,    cudaFuncAttributeMaxDynamicSharedMemorySize, DG_SMEM);

    dim3 blk(256);
    dim3 gT(HH / 128, BT / 128);
    dim3 gD(6, BT / 128);
    dim3 cblk(32, 8);

    // 0: all weight transposes + bf16 splits
    convw_all_kernel<<<4800, cblk>>>(W_r, W_k, W_v, W_o, wB, vB, aB, gB, wA, vA, aA, gA);

    // 1: token-shift mixes -> bf16 hi/lo
    prep_kernel<<<BTH / 4 / 256, 256>>>(hs, x_r, x_w, x_k, x_v, x_a, x_g);

    // 2-4: big projections
    tgemm_kernel<0><<<gT, blk, TG_SMEM>>>(xrH, xrL, WrH, WrL, rb,  BT, HH, HH, nullptr, nullptr, nullptr);
    tgemm_kernel<0><<<gT, blk, TG_SMEM>>>(xkH, xkL, WkH, WkL, kb,  BT, HH, HH, nullptr, nullptr, nullptr);
    tgemm_kernel<0><<<gT, blk, TG_SMEM>>>(xvH, xvL, WvH, WvL, v0b, BT, HH, HH, nullptr, nullptr, nullptr);

    // 5: batched LoRA/gate down-projections
    dgemm_kernel<<<gD, blk, DG_SMEM>>>();

    // 6-9: up-projections with fused epilogues
    tgemm_kernel<4><<<gT, blk, TG_SMEM>>>(t1H, t1L, wBH, wBL, ewb, BT, HH, 64, wb, nullptr, nullptr);
    tgemm_kernel<5><<<gT, blk, TG_SMEM>>>(t2H, t2L, vBH, vBL, vb2, BT, HH, 64, vb, v0b, vfi);
    tgemm_kernel<3><<<gT, blk, TG_SMEM>>>(t3H, t3L, aBH, aBL, ab2, BT, HH, 64, ab, nullptr, nullptr);
    tgemm_kernel<0><<<gT, blk, TG_SMEM>>>(t4H, t4L, gBH, gBL, gb2, BT, HH, 160, nullptr, nullptr, nullptr);

    // 10: kk normalize / k scale / scan coefficient vectors
    postproj_kernel<<<BT, 1024>>>(k_k, k_a);

    // 11: sequential RWKV7 scan (cp.async ring)
    scan_kernel<<<128, 256>>>();

    // 12: groupnorm + correction + gate -> y (bf16 hi/lo)
    finalmix_kernel<<<BT, 512>>>(r_k, gnw, gnb);

    // 13: output projection
    tgemm_kernel<0><<<gT, blk, TG_SMEM>>>(yH, yL, WoH, WoL, (float*)d_out, BT, HH, HH,
                                          nullptr, nullptr, nullptr);
}

// round 17
// speedup vs baseline: 1.9542x; 1.1179x over previous
#include <cuda_runtime.h>
#include <cuda_bf16.h>
#include <stdint.h>
#include <math.h>

// ---------------------------------------------------------------------------
// RWKV7 attention block, B=4 T=2048 H=1024 NH=16 HD=64.
// All GEMMs: mma.sync bf16 hi/lo split, fp32 accum, cp.async staging.
// r/k/v projections fused into one launch (grid.z); four up-projections fused
// into one launch. Scan: cp.async ring (10 slots), one barrier per 2 steps.
// ---------------------------------------------------------------------------

#define BB   4
#define TT   2048
#define HH   1024
#define HDD  64
#define NHH  16
#define BT   (BB*TT)        // 8192 tokens
#define BTH  (BT*HH)        // 8388608
#define DECAY_LOG_SCALE (-0.6065306597126334f)
#define GN_EPS (64.0f*1e-5f)

// ----------------------------- scratch ------------------------------------
static __device__ float g_r[BTH], g_ew[BTH], g_k[BTH], g_v0[BTH], g_v[BTH], g_a[BTH];
static __device__ float g_an[BTH], g_bv[BTH], g_g[BTH], g_o[BTH];
static __device__ __nv_bfloat16 g_xrH[BTH], g_xrL[BTH], g_xwH[BTH], g_xwL[BTH];
static __device__ __nv_bfloat16 g_xkH[BTH], g_xkL[BTH], g_xvH[BTH], g_xvL[BTH];
static __device__ __nv_bfloat16 g_xaH[BTH], g_xaL[BTH], g_xgH[BTH], g_xgL[BTH];
static __device__ __nv_bfloat16 g_t1H[BT*64], g_t1L[BT*64], g_t2H[BT*64], g_t2L[BT*64];
static __device__ __nv_bfloat16 g_t3H[BT*64], g_t3L[BT*64], g_t4H[BT*160], g_t4L[BT*160];
static __device__ __nv_bfloat16 g_yH[BTH], g_yL[BTH];

static __device__ __nv_bfloat16 g_WrH[HH*HH], g_WrL[HH*HH];
static __device__ __nv_bfloat16 g_WkH[HH*HH], g_WkL[HH*HH];
static __device__ __nv_bfloat16 g_WvH[HH*HH], g_WvL[HH*HH];
static __device__ __nv_bfloat16 g_WoH[HH*HH], g_WoL[HH*HH];
static __device__ __nv_bfloat16 g_wBH[HH*64], g_wBL[HH*64];
static __device__ __nv_bfloat16 g_vBH[HH*64], g_vBL[HH*64];
static __device__ __nv_bfloat16 g_aBH[HH*64], g_aBL[HH*64];
static __device__ __nv_bfloat16 g_gBH[HH*160], g_gBL[HH*160];
static __device__ __nv_bfloat16 g_wAH[64*HH], g_wAL[64*HH];
static __device__ __nv_bfloat16 g_vAH[64*HH], g_vAL[64*HH];
static __device__ __nv_bfloat16 g_aAH[64*HH], g_aAL[64*HH];
static __device__ __nv_bfloat16 g_gAH[160*HH], g_gAL[160*HH];

__device__ __forceinline__ float sigf(float x) { return 1.0f / (1.0f + expf(-x)); }

__device__ __forceinline__ uint32_t pack_bf2(__nv_bfloat16 lo, __nv_bfloat16 hi) {
    return (uint32_t)__bfloat16_as_ushort(lo) | ((uint32_t)__bfloat16_as_ushort(hi) << 16);
}

__device__ __forceinline__ uint32_t smem_u32(const void* p) {
    uint32_t a;
    asm("{ .reg .u64 t; cvta.to.shared.u64 t, %1; cvt.u32.u64 %0, t; }" : "=r"(a) : "l"(p));
    return a;
}

__device__ __forceinline__ void cpa16(uint32_t dst, const void* src) {
    asm volatile("cp.async.ca.shared.global [%0], [%1], 16;" :: "r"(dst), "l"(src));
}
#define CP_COMMIT() asm volatile("cp.async.commit_group;" ::: "memory")
#define CP_WAIT0()  asm volatile("cp.async.wait_group 0;" ::: "memory")

__device__ __forceinline__ void ldsm4(uint32_t& r0, uint32_t& r1, uint32_t& r2, uint32_t& r3,
                                      uint32_t addr)
{
    asm volatile("ldmatrix.sync.aligned.m8n8.x4.shared.b16 {%0,%1,%2,%3}, [%4];"
                 : "=r"(r0), "=r"(r1), "=r"(r2), "=r"(r3) : "r"(addr));
}

__device__ __forceinline__ void mma16816(float* c,
                                         uint32_t a0, uint32_t a1, uint32_t a2, uint32_t a3,
                                         uint32_t b0, uint32_t b1)
{
    asm volatile("mma.sync.aligned.m16n8k16.row.col.f32.bf16.bf16.f32 "
                 "{%0,%1,%2,%3}, {%4,%5,%6,%7}, {%8,%9}, {%0,%1,%2,%3};"
                 : "+f"(c[0]), "+f"(c[1]), "+f"(c[2]), "+f"(c[3])
                 : "r"(a0), "r"(a1), "r"(a2), "r"(a3), "r"(b0), "r"(b1));
}

// ----------------------------- prep: token shift -> bf16 hi/lo -------------
__global__ void prep_kernel(const float* __restrict__ hs,
                            const float* __restrict__ mr, const float* __restrict__ mw,
                            const float* __restrict__ mk, const float* __restrict__ mv,
                            const float* __restrict__ ma, const float* __restrict__ mg)
{
    int i4 = blockIdx.x * blockDim.x + threadIdx.x;
    if (i4 >= BTH / 4) return;
    int i = i4 * 4;
    int t = (i / HH) % TT;
    int h = i % HH;
    float4 x = *(const float4*)(hs + i);
    float4 p = make_float4(0.f, 0.f, 0.f, 0.f);
    if (t > 0) p = *(const float4*)(hs + i - HH);
    float4 d = make_float4(p.x - x.x, p.y - x.y, p.z - x.z, p.w - x.w);
#define DOMIX(dH, dL, mp) { \
    float4 m4 = *(const float4*)((mp) + h); float4 o4; \
    o4.x = fmaf(d.x, m4.x, x.x); o4.y = fmaf(d.y, m4.y, x.y); \
    o4.z = fmaf(d.z, m4.z, x.z); o4.w = fmaf(d.w, m4.w, x.w); \
    __nv_bfloat16 h0 = __float2bfloat16(o4.x), h1 = __float2bfloat16(o4.y); \
    __nv_bfloat16 h2 = __float2bfloat16(o4.z), h3 = __float2bfloat16(o4.w); \
    __nv_bfloat16 l0 = __float2bfloat16(o4.x - __bfloat162float(h0)); \
    __nv_bfloat16 l1 = __float2bfloat16(o4.y - __bfloat162float(h1)); \
    __nv_bfloat16 l2 = __float2bfloat16(o4.z - __bfloat162float(h2)); \
    __nv_bfloat16 l3 = __float2bfloat16(o4.w - __bfloat162float(h3)); \
    uint2 hv; hv.x = pack_bf2(h0, h1); hv.y = pack_bf2(h2, h3); \
    uint2 lv; lv.x = pack_bf2(l0, l1); lv.y = pack_bf2(l2, l3); \
    *(uint2*)((dH) + i) = hv; *(uint2*)((dL) + i) = lv; }
    DOMIX(g_xrH, g_xrL, mr) DOMIX(g_xwH, g_xwL, mw) DOMIX(g_xkH, g_xkL, mk)
    DOMIX(g_xvH, g_xvL, mv) DOMIX(g_xaH, g_xaL, ma) DOMIX(g_xgH, g_xgL, mg)
#undef DOMIX
}

// ----------------- weight transpose + bf16 hi/lo split (all-in-one) -------
__global__ void convw_all_kernel(const float* __restrict__ Wr, const float* __restrict__ Wk,
                                 const float* __restrict__ Wv, const float* __restrict__ Wo,
                                 const float* __restrict__ wB, const float* __restrict__ vB,
                                 const float* __restrict__ aB, const float* __restrict__ gB,
                                 const float* __restrict__ wA, const float* __restrict__ vA,
                                 const float* __restrict__ aA, const float* __restrict__ gA)
{
    __shared__ float ts[32][33];
    int bidx = blockIdx.x;
    const float* W; __nv_bfloat16 *Bh, *Bl;
    int SK, SN, nb, kb;
    if (bidx < 4096) {
        int m = bidx >> 10, local = bidx & 1023;
        SK = HH; SN = HH;
        nb = (local & 31) * 32; kb = (local >> 5) * 32;
        switch (m) {
            case 0: W = Wr; Bh = g_WrH; Bl = g_WrL; break;
            case 1: W = Wk; Bh = g_WkH; Bl = g_WkL; break;
            case 2: W = Wv; Bh = g_WvH; Bl = g_WvL; break;
            default: W = Wo; Bh = g_WoH; Bl = g_WoL; break;
        }
    } else if (bidx < 4288) {
        int m = (bidx - 4096) >> 6, local = (bidx - 4096) & 63;
        SK = 64; SN = HH;
        nb = (local & 31) * 32; kb = (local >> 5) * 32;
        switch (m) {
            case 0: W = wB; Bh = g_wBH; Bl = g_wBL; break;
            case 1: W = vB; Bh = g_vBH; Bl = g_vBL; break;
            default: W = aB; Bh = g_aBH; Bl = g_aBL; break;
        }
    } else if (bidx < 4448) {
        int local = bidx - 4288;
        SK = 160; SN = HH;
        nb = (local & 31) * 32; kb = (local >> 5) * 32;
        W = gB; Bh = g_gBH; Bl = g_gBL;
    } else if (bidx < 4640) {
        int m = (bidx - 4448) >> 6, local = (bidx - 4448) & 63;
        SK = HH; SN = 64;
        nb = (local & 1) * 32; kb = (local >> 1) * 32;
        switch (m) {
            case 0: W = wA; Bh = g_wAH; Bl = g_wAL; break;
            case 1: W = vA; Bh = g_vAH; Bl = g_vAL; break;
            default: W = aA; Bh = g_aAH; Bl = g_aAL; break;
        }
    } else {
        int local = bidx - 4640;
        SK = HH; SN = 160;
        nb = (local % 5) * 32; kb = (local / 5) * 32;
        W = gA; Bh = g_gAH; Bl = g_gAL;
    }
    int tx = threadIdx.x, ty = threadIdx.y;  // 32 x 8
    for (int i = ty; i < 32; i += 8)
        ts[i][tx] = W[(size_t)(kb + i) * SN + nb + tx];
    __syncthreads();
    for (int i = ty; i < 32; i += 8) {
        float x = ts[tx][i];
        __nv_bfloat16 h = __float2bfloat16(x);
        __nv_bfloat16 l = __float2bfloat16(x - __bfloat162float(h));
        size_t o = (size_t)(nb + i) * SK + kb + tx;
        Bh[o] = h; Bl[o] = l;
    }
}

// --------------------- shared GEMM core macros -----------------------------
#define LDS 40                       // padded row length (bf16 elems)
#define ABUF (128*LDS)
#define TG_SMEM (8*ABUF*2)           // 81920 B

#define T_LOAD_G(kc, b, Ahp, Alp, Bhp, Blp, Kv) { \
        int k0 = (kc) << 5; \
        uint32_t aH = sA + (b) * (4 * ABUF); \
        uint32_t bH = sB + (b) * (4 * ABUF); \
        _Pragma("unroll") \
        for (int i = 0; i < 2; i++) { \
            int idx = tid + i * 256; \
            int r = idx >> 2, c = (idx & 3) << 3; \
            uint32_t so = (uint32_t)(r * LDS + c) * 2; \
            size_t ga = (size_t)(m0 + r) * (Kv) + k0 + c; \
            size_t gb = (size_t)(n0 + r) * (Kv) + k0 + c; \
            cpa16(aH + so, (Ahp) + ga); \
            cpa16(aH + 2 * ABUF + so, (Alp) + ga); \
            cpa16(bH + so, (Bhp) + gb); \
            cpa16(bH + 2 * ABUF + so, (Blp) + gb); \
        } }

#define T_COMPUTE(buf) { \
        uint32_t aBaseH = sA + (buf) * (4 * ABUF); \
        uint32_t aBaseL = aBaseH + 2 * ABUF; \
        uint32_t bBaseH = sB + (buf) * (4 * ABUF); \
        uint32_t bBaseL = bBaseH + 2 * ABUF; \
        _Pragma("unroll") \
        for (int kk = 0; kk < 32; kk += 16) { \
            uint32_t ah[4][4], al[4][4], bh[2][4], bl[2][4]; \
            _Pragma("unroll") \
            for (int i = 0; i < 4; i++) { \
                int row = wm * 64 + i * 16 + (lane & 15); \
                int col = kk + ((lane >> 4) << 3); \
                uint32_t off = (uint32_t)(row * LDS + col) * 2; \
                ldsm4(ah[i][0], ah[i][1], ah[i][2], ah[i][3], aBaseH + off); \
                ldsm4(al[i][0], al[i][1], al[i][2], al[i][3], aBaseL + off); \
            } \
            _Pragma("unroll") \
            for (int jp = 0; jp < 2; jp++) { \
                int row = wn * 32 + jp * 16 + ((lane >> 4) << 3) + (lane & 7); \
                int col = kk + ((lane >> 3) & 1) * 8; \
                uint32_t off = (uint32_t)(row * LDS + col) * 2; \
                ldsm4(bh[jp][0], bh[jp][1], bh[jp][2], bh[jp][3], bBaseH + off); \
                ldsm4(bl[jp][0], bl[jp][1], bl[jp][2], bl[jp][3], bBaseL + off); \
            } \
            _Pragma("unroll") \
            for (int i = 0; i < 4; i++) \
                _Pragma("unroll") \
                for (int j = 0; j < 4; j++) { \
                    uint32_t b0h = bh[j >> 1][(j & 1) * 2], b1h = bh[j >> 1][(j & 1) * 2 + 1]; \
                    uint32_t b0l = bl[j >> 1][(j & 1) * 2], b1l = bl[j >> 1][(j & 1) * 2 + 1]; \
                    mma16816(acc[i][j], ah[i][0], ah[i][1], ah[i][2], ah[i][3], b0h, b1h); \
                    mma16816(acc[i][j], ah[i][0], ah[i][1], ah[i][2], ah[i][3], b0l, b1l); \
                    mma16816(acc[i][j], al[i][0], al[i][1], al[i][2], al[i][3], b0h, b1h); \
                } \
        } }

// -------------- fused r/k/v projections (grid.z = 0..2, EPI none) ----------
__global__ void __launch_bounds__(256, 2)
tgemm3_kernel()
{
    extern __shared__ char smem[];
    const uint32_t sA = smem_u32(smem);
    const uint32_t sB = sA + 4 * ABUF * 2;
    const int tid = threadIdx.x;
    const int wid = tid >> 5, lane = tid & 31;
    const int wm = wid >> 2, wn = wid & 3;
    const int m0 = blockIdx.y * 128, n0 = blockIdx.x * 128;

    const __nv_bfloat16 *Ah, *Al, *Bh, *Bl; float* C;
    switch (blockIdx.z) {
        case 0:  Ah = g_xrH; Al = g_xrL; Bh = g_WrH; Bl = g_WrL; C = g_r;  break;
        case 1:  Ah = g_xkH; Al = g_xkL; Bh = g_WkH; Bl = g_WkL; C = g_k;  break;
        default: Ah = g_xvH; Al = g_xvL; Bh = g_WvH; Bl = g_WvL; C = g_v0; break;
    }
    const int K = HH, N = HH;
    const int nC = K >> 5;

    float acc[4][4][4];
#pragma unroll
    for (int i = 0; i < 4; i++)
#pragma unroll
        for (int j = 0; j < 4; j++)
#pragma unroll
            for (int f = 0; f < 4; f++) acc[i][j][f] = 0.f;

    T_LOAD_G(0, 0, Ah, Al, Bh, Bl, K)
    CP_COMMIT();
    CP_WAIT0();
    __syncthreads();

    for (int ic = 0; ic < nC; ic++) {
        int buf = ic & 1;
        if (ic + 1 < nC) { T_LOAD_G(ic + 1, buf ^ 1, Ah, Al, Bh, Bl, K) CP_COMMIT(); }
        T_COMPUTE(buf)
        if (ic + 1 < nC) { CP_WAIT0(); __syncthreads(); }
    }

    int g = lane >> 2, tig = lane & 3;
#pragma unroll
    for (int i = 0; i < 4; i++) {
        int r0 = m0 + wm * 64 + i * 16 + g;
#pragma unroll
        for (int j = 0; j < 4; j++) {
            int col = n0 + wn * 32 + j * 8 + tig * 2;
            *(float2*)(C + (size_t)r0 * N + col) = make_float2(acc[i][j][0], acc[i][j][1]);
            *(float2*)(C + (size_t)(r0 + 8) * N + col) = make_float2(acc[i][j][2], acc[i][j][3]);
        }
    }
}

// -------------- fused up-projections (grid.z = 0..3, runtime EPI) ----------
__global__ void __launch_bounds__(256, 2)
upproj_kernel(const float* __restrict__ wb, const float* __restrict__ vb,
              const float* __restrict__ ab, const float* __restrict__ vfi)
{
    extern __shared__ char smem[];
    const uint32_t sA = smem_u32(smem);
    const uint32_t sB = sA + 4 * ABUF * 2;
    const int tid = threadIdx.x;
    const int wid = tid >> 5, lane = tid & 31;
    const int wm = wid >> 2, wn = wid & 3;
    const int m0 = blockIdx.y * 128, n0 = blockIdx.x * 128;

    const __nv_bfloat16 *Ah, *Al, *Bh, *Bl; float* C;
    const float* bias = nullptr;
    int K, epi;
    switch (blockIdx.z) {
        case 0:  Ah = g_t1H; Al = g_t1L; Bh = g_wBH; Bl = g_wBL; C = g_ew; K = 64;  epi = 4; bias = wb; break;
        case 1:  Ah = g_t2H; Al = g_t2L; Bh = g_vBH; Bl = g_vBL; C = g_v;  K = 64;  epi = 5; bias = vb; break;
        case 2:  Ah = g_t3H; Al = g_t3L; Bh = g_aBH; Bl = g_aBL; C = g_a;  K = 64;  epi = 3; bias = ab; break;
        default: Ah = g_t4H; Al = g_t4L; Bh = g_gBH; Bl = g_gBL; C = g_g;  K = 160; epi = 0; break;
    }
    const int N = HH;
    const int nC = K >> 5;

    float acc[4][4][4];
#pragma unroll
    for (int i = 0; i < 4; i++)
#pragma unroll
        for (int j = 0; j < 4; j++)
#pragma unroll
            for (int f = 0; f < 4; f++) acc[i][j][f] = 0.f;

    T_LOAD_G(0, 0, Ah, Al, Bh, Bl, K)
    CP_COMMIT();
    CP_WAIT0();
    __syncthreads();

    for (int ic = 0; ic < nC; ic++) {
        int buf = ic & 1;
        if (ic + 1 < nC) { T_LOAD_G(ic + 1, buf ^ 1, Ah, Al, Bh, Bl, K) CP_COMMIT(); }
        T_COMPUTE(buf)
        if (ic + 1 < nC) { CP_WAIT0(); __syncthreads(); }
    }

    int g = lane >> 2, tig = lane & 3;
#pragma unroll
    for (int i = 0; i < 4; i++) {
        int r0 = m0 + wm * 64 + i * 16 + g;
#pragma unroll
        for (int j = 0; j < 4; j++) {
            int col = n0 + wn * 32 + j * 8 + tig * 2;
            float2 v0 = make_float2(acc[i][j][0], acc[i][j][1]);
            float2 v1 = make_float2(acc[i][j][2], acc[i][j][3]);
            if (epi != 0) {
                float b0 = bias[col], b1 = bias[col + 1];
                v0.x = sigf(v0.x + b0); v0.y = sigf(v0.y + b1);
                v1.x = sigf(v1.x + b0); v1.y = sigf(v1.y + b1);
                if (epi == 4) {
                    v0.x = expf(DECAY_LOG_SCALE * v0.x); v0.y = expf(DECAY_LOG_SCALE * v0.y);
                    v1.x = expf(DECAY_LOG_SCALE * v1.x); v1.y = expf(DECAY_LOG_SCALE * v1.y);
                } else if (epi == 5) {
                    size_t o0 = (size_t)r0 * N + col, o1 = (size_t)(r0 + 8) * N + col;
                    float2 a0 = *(const float2*)(g_v0 + o0);
                    float2 c0v = *(const float2*)(vfi + o0);
                    float2 a1 = *(const float2*)(g_v0 + o1);
                    float2 c1v = *(const float2*)(vfi + o1);
                    v0.x = fmaf(v0.x, c0v.x - a0.x, a0.x);
                    v0.y = fmaf(v0.y, c0v.y - a0.y, a0.y);
                    v1.x = fmaf(v1.x, c1v.x - a1.x, a1.x);
                    v1.y = fmaf(v1.y, c1v.y - a1.y, a1.y);
                }
            }
            *(float2*)(C + (size_t)r0 * N + col) = v0;
            *(float2*)(C + (size_t)(r0 + 8) * N + col) = v1;
        }
    }
}

// -------------- o-projection (single, EPI none) ----------------------------
__global__ void __launch_bounds__(256, 2)
ogemm_kernel(float* __restrict__ C)
{
    extern __shared__ char smem[];
    const uint32_t sA = smem_u32(smem);
    const uint32_t sB = sA + 4 * ABUF * 2;
    const int tid = threadIdx.x;
    const int wid = tid >> 5, lane = tid & 31;
    const int wm = wid >> 2, wn = wid & 3;
    const int m0 = blockIdx.y * 128, n0 = blockIdx.x * 128;
    const __nv_bfloat16 *Ah = g_yH, *Al = g_yL, *Bh = g_WoH, *Bl = g_WoL;
    const int K = HH, N = HH;
    const int nC = K >> 5;

    float acc[4][4][4];
#pragma unroll
    for (int i = 0; i < 4; i++)
#pragma unroll
        for (int j = 0; j < 4; j++)
#pragma unroll
            for (int f = 0; f < 4; f++) acc[i][j][f] = 0.f;

    T_LOAD_G(0, 0, Ah, Al, Bh, Bl, K)
    CP_COMMIT();
    CP_WAIT0();
    __syncthreads();

    for (int ic = 0; ic < nC; ic++) {
        int buf = ic & 1;
        if (ic + 1 < nC) { T_LOAD_G(ic + 1, buf ^ 1, Ah, Al, Bh, Bl, K) CP_COMMIT(); }
        T_COMPUTE(buf)
        if (ic + 1 < nC) { CP_WAIT0(); __syncthreads(); }
    }

    int g = lane >> 2, tig = lane & 3;
#pragma unroll
    for (int i = 0; i < 4; i++) {
        int r0 = m0 + wm * 64 + i * 16 + g;
#pragma unroll
        for (int j = 0; j < 4; j++) {
            int col = n0 + wn * 32 + j * 8 + tig * 2;
            *(float2*)(C + (size_t)r0 * N + col) = make_float2(acc[i][j][0], acc[i][j][1]);
            *(float2*)(C + (size_t)(r0 + 8) * N + col) = make_float2(acc[i][j][2], acc[i][j][3]);
        }
    }
}

// ------------- batched down-projection GEMM (mma, 128x64 tiles) ------------
#define DBBUF (64*LDS)
#define DG_SMEM ((4*ABUF + 4*DBBUF)*2)   // 61440 B

__global__ void __launch_bounds__(256, 2)
dgemm_kernel()
{
    extern __shared__ char smem[];
    const uint32_t sA = smem_u32(smem);
    const uint32_t sB = sA + 4 * ABUF * 2;
    const int tid = threadIdx.x;
    const int wid = tid >> 5, lane = tid & 31;
    const int wm = wid & 3, wn = (wid >> 2) & 1;
    const int m0 = blockIdx.y * 128;
    const int tix = blockIdx.x;

    const __nv_bfloat16 *Ah, *Al, *BH, *BL;
    __nv_bfloat16 *CH, *CL;
    int Nseg, n0, epi;
    if (tix == 0)      { Ah = g_xwH; Al = g_xwL; BH = g_wAH; BL = g_wAL; CH = g_t1H; CL = g_t1L; Nseg = 64;  n0 = 0; epi = 1; }
    else if (tix == 1) { Ah = g_xvH; Al = g_xvL; BH = g_vAH; BL = g_vAL; CH = g_t2H; CL = g_t2L; Nseg = 64;  n0 = 0; epi = 0; }
    else if (tix == 2) { Ah = g_xaH; Al = g_xaL; BH = g_aAH; BL = g_aAL; CH = g_t3H; CL = g_t3L; Nseg = 64;  n0 = 0; epi = 0; }
    else               { Ah = g_xgH; Al = g_xgL; BH = g_gAH; BL = g_gAL; CH = g_t4H; CL = g_t4L; Nseg = 160; n0 = (tix - 3) * 64; epi = 2; }

    const int K = HH;
    float acc[2][4][4];
#pragma unroll
    for (int i = 0; i < 2; i++)
#pragma unroll
        for (int j = 0; j < 4; j++)
#pragma unroll
            for (int f = 0; f < 4; f++) acc[i][j][f] = 0.f;

    const int nC = K >> 5;
    const int brow = tid >> 2, bc = (tid & 3) << 3;
    const bool bvalid = (n0 + brow) < Nseg;

    if (!bvalid) {
#pragma unroll
        for (int b = 0; b < 2; b++) {
            uint32_t bH = sB + b * (4 * DBBUF);
            uint32_t so = (uint32_t)(brow * LDS + bc) * 2;
            *(uint4*)(smem + (bH - sA) + so) = make_uint4(0, 0, 0, 0);
            *(uint4*)(smem + (bH + 2 * DBBUF - sA) + so) = make_uint4(0, 0, 0, 0);
        }
    }
    __syncthreads();

#define D_LOAD(kc, b) { \
        int k0 = (kc) << 5; \
        uint32_t aH = sA + (b) * (4 * ABUF); \
        uint32_t bH = sB + (b) * (4 * DBBUF); \
        _Pragma("unroll") \
        for (int i = 0; i < 2; i++) { \
            int idx = tid + i * 256; \
            int r = idx >> 2, c = (idx & 3) << 3; \
            uint32_t so = (uint32_t)(r * LDS + c) * 2; \
            size_t ga = (size_t)(m0 + r) * K + k0 + c; \
            cpa16(aH + so, Ah + ga); \
            cpa16(aH + 2 * ABUF + so, Al + ga); \
        } \
        if (bvalid) { \
            uint32_t so = (uint32_t)(brow * LDS + bc) * 2; \
            size_t gb = (size_t)(n0 + brow) * K + k0 + bc; \
            cpa16(bH + so, BH + gb); \
            cpa16(bH + 2 * DBBUF + so, BL + gb); \
        } }

    D_LOAD(0, 0)
    CP_COMMIT();
    CP_WAIT0();
    __syncthreads();

    for (int ic = 0; ic < nC; ic++) {
        int buf = ic & 1;
        if (ic + 1 < nC) { D_LOAD(ic + 1, buf ^ 1) CP_COMMIT(); }

        {
            uint32_t aBaseH = sA + buf * (4 * ABUF);
            uint32_t aBaseL = aBaseH + 2 * ABUF;
            uint32_t bBaseH = sB + buf * (4 * DBBUF);
            uint32_t bBaseL = bBaseH + 2 * DBBUF;
#pragma unroll
            for (int kk = 0; kk < 32; kk += 16) {
                uint32_t ah[2][4], al[2][4], bh[2][4], bl[2][4];
#pragma unroll
                for (int i = 0; i < 2; i++) {
                    int row = wm * 32 + i * 16 + (lane & 15);
                    int col = kk + ((lane >> 4) << 3);
                    uint32_t off = (uint32_t)(row * LDS + col) * 2;
                    ldsm4(ah[i][0], ah[i][1], ah[i][2], ah[i][3], aBaseH + off);
                    ldsm4(al[i][0], al[i][1], al[i][2], al[i][3], aBaseL + off);
                }
#pragma unroll
                for (int jp = 0; jp < 2; jp++) {
                    int row = wn * 32 + jp * 16 + ((lane >> 4) << 3) + (lane & 7);
                    int col = kk + ((lane >> 3) & 1) * 8;
                    uint32_t off = (uint32_t)(row * LDS + col) * 2;
                    ldsm4(bh[jp][0], bh[jp][1], bh[jp][2], bh[jp][3], bBaseH + off);
                    ldsm4(bl[jp][0], bl[jp][1], bl[jp][2], bl[jp][3], bBaseL + off);
                }
#pragma unroll
                for (int i = 0; i < 2; i++)
#pragma unroll
                    for (int j = 0; j < 4; j++) {
                        uint32_t b0h = bh[j >> 1][(j & 1) * 2], b1h = bh[j >> 1][(j & 1) * 2 + 1];
                        uint32_t b0l = bl[j >> 1][(j & 1) * 2], b1l = bl[j >> 1][(j & 1) * 2 + 1];
                        mma16816(acc[i][j], ah[i][0], ah[i][1], ah[i][2], ah[i][3], b0h, b1h);
                        mma16816(acc[i][j], ah[i][0], ah[i][1], ah[i][2], ah[i][3], b0l, b1l);
                        mma16816(acc[i][j], al[i][0], al[i][1], al[i][2], al[i][3], b0h, b1h);
                    }
            }
        }

        if (ic + 1 < nC) {
            CP_WAIT0();
            __syncthreads();
        }
    }

    int g = lane >> 2, tig = lane & 3;
#pragma unroll
    for (int i = 0; i < 2; i++) {
        int r0 = m0 + wm * 32 + i * 16 + g;
#pragma unroll
        for (int j = 0; j < 4; j++) {
            int gcol = n0 + wn * 32 + j * 8 + tig * 2;
            if (gcol >= Nseg) continue;
            float2 v0 = make_float2(acc[i][j][0], acc[i][j][1]);
            float2 v1 = make_float2(acc[i][j][2], acc[i][j][3]);
            if (epi == 1) {
                v0.x = tanhf(v0.x); v0.y = tanhf(v0.y);
                v1.x = tanhf(v1.x); v1.y = tanhf(v1.y);
            } else if (epi == 2) {
                v0.x = sigf(v0.x); v0.y = sigf(v0.y);
                v1.x = sigf(v1.x); v1.y = sigf(v1.y);
            }
#define STORE_HL(val2, roff) { \
            __nv_bfloat16 h0 = __float2bfloat16((val2).x), h1 = __float2bfloat16((val2).y); \
            __nv_bfloat16 l0 = __float2bfloat16((val2).x - __bfloat162float(h0)); \
            __nv_bfloat16 l1 = __float2bfloat16((val2).y - __bfloat162float(h1)); \
            size_t oo = (size_t)(roff) * Nseg + gcol; \
            *(uint32_t*)(CH + oo) = pack_bf2(h0, h1); \
            *(uint32_t*)(CL + oo) = pack_bf2(l0, l1); }
            STORE_HL(v0, r0)
            STORE_HL(v1, r0 + 8)
#undef STORE_HL
        }
    }
}

// --------------------- postproj: kk-normalize, k scale, a/b vecs -----------
__global__ void postproj_kernel(const float* __restrict__ kkw,
                                const float* __restrict__ kaw)
{
    int bt = blockIdx.x;
    int h = threadIdx.x;
    int head = h >> 6;
    int idx = bt * HH + h;
    float kv = g_k[idx], av = g_a[idx];
    float kkx = kv * kkw[h];
    float ss = kkx * kkx;
#pragma unroll
    for (int m = 16; m >= 1; m >>= 1) ss += __shfl_xor_sync(~0u, ss, m);
    __shared__ float ws[32];
    if ((h & 31) == 0) ws[h >> 5] = ss;
    __syncthreads();
    float tot = ws[head * 2] + ws[head * 2 + 1];
    float inv = 1.0f / fmaxf(sqrtf(tot), 1e-12f);
    float kkn = kkx * inv;
    g_an[idx] = -kkn;
    g_bv[idx] = kkn * av;
    g_k[idx] = kv * (1.0f + (av - 1.0f) * kaw[h]);
}

// ------------- scan: cp.async ring, 10 slots, barrier per 2 steps ----------
__global__ void __launch_bounds__(256) scan_kernel()
{
    __shared__ float sh[10][6][64];   // 15 KB ring
    int pair = blockIdx.x >> 1;
    int rsplit = blockIdx.x & 1;
    int tid = threadIdx.x;
    int vloc = tid >> 3;
    int q = tid & 7;
    int vrow = rsplit * 32 + vloc;
    int b = pair >> 4, h = pair & 15;
    int base0 = b * TT * HH + h * HDD;

    const float* lp = nullptr;
    int aid = 0, wq = 0;
    const bool ldr = tid < 96;
    if (ldr) {
        aid = tid >> 4; wq = tid & 15;
        switch (aid) {
            case 0: lp = g_r;  break;
            case 1: lp = g_ew; break;
            case 2: lp = g_k;  break;
            case 3: lp = g_v;  break;
            case 4: lp = g_an; break;
            default: lp = g_bv; break;
        }
        lp += base0 + (wq << 2);
    }
    const uint32_t sbase = smem_u32(&sh[0][0][0]);
    const uint32_t soff = (uint32_t)((aid * 64 + (wq << 2)) * 4);
    const uint32_t SLOT = 6 * 64 * 4;   // 1536 B

    float S[8];
#pragma unroll
    for (int j = 0; j < 8; j++) S[j] = 0.f;

    // prologue: 3 groups covering steps (0,1),(2,3),(4,5)
#pragma unroll
    for (int s = 0; s < 3; s++) {
        if (ldr) {
            cpa16(sbase + (uint32_t)(2 * s) * SLOT + soff, lp + (size_t)(2 * s) * HH);
            cpa16(sbase + (uint32_t)(2 * s + 1) * SLOT + soff, lp + (size_t)(2 * s + 1) * HH);
        }
        CP_COMMIT();
    }

    int slot0 = 0;     // slot of step t (t = 2*P)
    int slotW = 6;     // slot of step t+6
    for (int t = 0; t < TT; t += 2) {
        // issue prefetch for steps t+6, t+7 (one group)
        if (ldr && t + 6 < TT) {
            int slotW1 = slotW + 1; if (slotW1 >= 10) slotW1 -= 10;
            cpa16(sbase + (uint32_t)slotW * SLOT + soff, lp + (size_t)(t + 6) * HH);
            cpa16(sbase + (uint32_t)slotW1 * SLOT + soff, lp + (size_t)(t + 7) * HH);
        }
        CP_COMMIT();
        asm volatile("cp.async.wait_group 3;" ::: "memory");
        __syncthreads();

        int slot1 = slot0 + 1; if (slot1 >= 10) slot1 -= 10;
#pragma unroll
        for (int s = 0; s < 2; s++) {
            const float (*cs)[64] = sh[s == 0 ? slot0 : slot1];
            int c0 = q << 3;

            float4 aA = *(const float4*)&cs[4][c0];
            float4 aB = *(const float4*)&cs[4][c0 + 4];
            float sa = S[0]*aA.x + S[1]*aA.y + S[2]*aA.z + S[3]*aA.w
                     + S[4]*aB.x + S[5]*aB.y + S[6]*aB.z + S[7]*aB.w;
            sa += __shfl_xor_sync(~0u, sa, 1);
            sa += __shfl_xor_sync(~0u, sa, 2);
            sa += __shfl_xor_sync(~0u, sa, 4);

            float vv = cs[3][vrow];
            float4 eA = *(const float4*)&cs[1][c0];
            float4 eB = *(const float4*)&cs[1][c0 + 4];
            float4 kA = *(const float4*)&cs[2][c0];
            float4 kB = *(const float4*)&cs[2][c0 + 4];
            float4 bA = *(const float4*)&cs[5][c0];
            float4 bB = *(const float4*)&cs[5][c0 + 4];

            S[0] = fmaf(S[0], eA.x, fmaf(sa, bA.x, vv * kA.x));
            S[1] = fmaf(S[1], eA.y, fmaf(sa, bA.y, vv * kA.y));
            S[2] = fmaf(S[2], eA.z, fmaf(sa, bA.z, vv * kA.z));
            S[3] = fmaf(S[3], eA.w, fmaf(sa, bA.w, vv * kA.w));
            S[4] = fmaf(S[4], eB.x, fmaf(sa, bB.x, vv * kB.x));
            S[5] = fmaf(S[5], eB.y, fmaf(sa, bB.y, vv * kB.y));
            S[6] = fmaf(S[6], eB.z, fmaf(sa, bB.z, vv * kB.z));
            S[7] = fmaf(S[7], eB.w, fmaf(sa, bB.w, vv * kB.w));

            float4 rA = *(const float4*)&cs[0][c0];
            float4 rB = *(const float4*)&cs[0][c0 + 4];
            float oo = S[0]*rA.x + S[1]*rA.y + S[2]*rA.z + S[3]*rA.w
                     + S[4]*rB.x + S[5]*rB.y + S[6]*rB.z + S[7]*rB.w;
            oo += __shfl_xor_sync(~0u, oo, 1);
            oo += __shfl_xor_sync(~0u, oo, 2);
            oo += __shfl_xor_sync(~0u, oo, 4);
            if (q == 0) g_o[base0 + (t + s) * HH + vrow] = oo;
        }

        slot0 += 2; if (slot0 >= 10) slot0 -= 10;
        slotW += 2; if (slotW >= 10) slotW -= 10;
    }
}

// ---------------- groupnorm + bonus-corr + gate -> y (bf16 hi/lo) ----------
__global__ void finalmix_kernel(const float* __restrict__ rkw,
                                const float* __restrict__ gnw,
                                const float* __restrict__ gnb)
{
    int bt = blockIdx.x;
    int head = threadIdx.x >> 5;
    int ld = threadIdx.x & 31;
    int base = bt * HH + head * HDD;
    int i0 = base + ld, i1 = base + 32 + ld;
    float o0 = g_o[i0], o1 = g_o[i1];
    float r0 = g_r[i0], r1 = g_r[i1];
    float k0 = g_k[i0], k1 = g_k[i1];
    float v0 = g_v[i0], v1 = g_v[i1];
    int h0 = head * HDD + ld, h1 = h0 + 32;

    float s  = o0 + o1;
    float qq = o0 * o0 + o1 * o1;
    float rk = r0 * k0 * rkw[h0] + r1 * k1 * rkw[h1];
#pragma unroll
    for (int m = 16; m >= 1; m >>= 1) {
        s  += __shfl_xor_sync(~0u, s,  m);
        qq += __shfl_xor_sync(~0u, qq, m);
        rk += __shfl_xor_sync(~0u, rk, m);
    }
    float mu = s * (1.0f / 64.0f);
    float var = qq * (1.0f / 64.0f) - mu * mu;
    float is = rsqrtf(var + GN_EPS);
    float y0 = (fmaf((o0 - mu) * is, gnw[h0], gnb[h0]) + rk * v0) * g_g[i0];
    float y1 = (fmaf((o1 - mu) * is, gnw[h1], gnb[h1]) + rk * v1) * g_g[i1];
    __nv_bfloat16 yh0 = __float2bfloat16(y0);
    __nv_bfloat16 yh1 = __float2bfloat16(y1);
    g_yH[i0] = yh0; g_yL[i0] = __float2bfloat16(y0 - __bfloat162float(yh0));
    g_yH[i1] = yh1; g_yL[i1] = __float2bfloat16(y1 - __bfloat162float(yh1));
}

// ----------------------------- host ----------------------------------------
extern "C" void kernel_launch(void* const* d_in, const int* in_sizes, int n_in,
                              void* d_out, int out_size)
{
    const float* hs  = (const float*)d_in[0];
    const float* vfi = (const float*)d_in[1];
    const float* x_r = (const float*)d_in[2];
    const float* x_w = (const float*)d_in[3];
    const float* x_k = (const float*)d_in[4];
    const float* x_v = (const float*)d_in[5];
    const float* x_a = (const float*)d_in[6];
    const float* x_g = (const float*)d_in[7];
    const float* k_k = (const float*)d_in[8];
    const float* k_a = (const float*)d_in[9];
    const float* r_k = (const float*)d_in[10];
    const float* W_r = (const float*)d_in[11];
    const float* W_k = (const float*)d_in[12];
    const float* W_v = (const float*)d_in[13];
    const float* W_o = (const float*)d_in[14];
    const float* wA  = (const float*)d_in[15];
    const float* wB  = (const float*)d_in[16];
    const float* wb  = (const float*)d_in[17];
    const float* vA  = (const float*)d_in[18];
    const float* vB  = (const float*)d_in[19];
    const float* vb  = (const float*)d_in[20];
    const float* aA  = (const float*)d_in[21];
    const float* aB  = (const float*)d_in[22];
    const float* ab  = (const float*)d_in[23];
    const float* gA  = (const float*)d_in[24];
    const float* gB  = (const float*)d_in[25];
    const float* gnw = (const float*)d_in[26];
    const float* gnb = (const float*)d_in[27];

    cudaFuncSetAttribute(tgemm3_kernel, cudaFuncAttributeMaxDynamicSharedMemorySize, TG_SMEM);
    cudaFuncSetAttribute(upproj_kernel, cudaFuncAttributeMaxDynamicSharedMemorySize, TG_SMEM);
    cudaFuncSetAttribute(ogemm_kernel,  cudaFuncAttributeMaxDynamicSharedMemorySize, TG_SMEM);
    cudaFuncSetAttribute(dgemm_kernel,  cudaFuncAttributeMaxDynamicSharedMemorySize, DG_SMEM);

    dim3 blk(256);
    dim3 gT3(HH / 128, BT / 128, 3);
    dim3 gUp(HH / 128, BT / 128, 4);
    dim3 gT(HH / 128, BT / 128);
    dim3 gD(6, BT / 128);
    dim3 cblk(32, 8);

    // 0: all weight transposes + bf16 splits
    convw_all_kernel<<<4800, cblk>>>(W_r, W_k, W_v, W_o, wB, vB, aB, gB, wA, vA, aA, gA);

    // 1: token-shift mixes -> bf16 hi/lo
    prep_kernel<<<BTH / 4 / 256, 256>>>(hs, x_r, x_w, x_k, x_v, x_a, x_g);

    // 2: fused r/k/v projections
    tgemm3_kernel<<<gT3, blk, TG_SMEM>>>();

    // 3: batched LoRA/gate down-projections
    dgemm_kernel<<<gD, blk, DG_SMEM>>>();

    // 4: fused up-projections (w/v/a/g) with epilogues
    upproj_kernel<<<gUp, blk, TG_SMEM>>>(wb, vb, ab, vfi);

    // 5: kk normalize / k scale / scan coefficient vectors
    postproj_kernel<<<BT, 1024>>>(k_k, k_a);

    // 6: sequential RWKV7 scan (cp.async ring, paired steps)
    scan_kernel<<<128, 256>>>();

    // 7: groupnorm + correction + gate -> y (bf16 hi/lo)
    finalmix_kernel<<<BT, 512>>>(r_k, gnw, gnb);

    // 8: output projection
    ogemm_kernel<<<gT, blk, TG_SMEM>>>((float*)d_out);
}